// round 1
// baseline (speedup 1.0000x reference)
#include <cuda_runtime.h>
#include <math.h>

#define Bn 4
#define Cn 64
#define Hn 192
#define Wn 192
#define HW (Hn*Wn)      // 36864
#define CM 256          // C*EXP
#define CH 32           // C/2

// ---------------- scratch (static device globals; no allocation) ----------------
__device__ float g_om  [Bn*27*HW];
__device__ float g_xd  [Bn*Cn*HW];
__device__ float g_mean[Bn*Cn];
__device__ float g_ca  [Bn*Cn];
__device__ float g_xa  [Bn*Cn*HW];
__device__ float g_t1  [Bn*CM*HW];
__device__ float g_xr  [Bn*Cn*HW];
__device__ float g_n1  [Bn*CH*HW];
__device__ float g_n2  [Bn*CH*HW];
// transposed weights: [kc][co] layouts for float4 co-blocked reads
__device__ float g_wdcT[576*64];
__device__ float g_wr2T[2304*64];
__device__ float g_wr1T[64*256];
__device__ float g_wn1T[64*32];
__device__ float g_wn3T[32*64];

__device__ __forceinline__ float sigmoidf_(float v){ return 1.f/(1.f+expf(-v)); }
__device__ __forceinline__ float leakyf_(float v){ return v >= 0.f ? v : 0.1f*v; }

// ---------------- weight transposes ----------------
__global__ void k_prep(const float* __restrict__ wdc, const float* __restrict__ wr2,
                       const float* __restrict__ wr1, const float* __restrict__ wn1,
                       const float* __restrict__ wn3){
    int stride = gridDim.x*blockDim.x;
    int i0 = blockIdx.x*blockDim.x + threadIdx.x;
    for (int t=i0; t<576*64;  t+=stride){ int kc=t>>6, co=t&63; g_wdcT[t] = wdc[co*576 + kc]; }
    for (int t=i0; t<2304*64; t+=stride){ int kc=t>>6, co=t&63; g_wr2T[t] = wr2[co*2304 + kc]; }
    for (int t=i0; t<64*256;  t+=stride){ int ci=t>>8, co=t&255; g_wr1T[t] = wr1[co*64 + ci]; }
    for (int t=i0; t<64*32;   t+=stride){ int ci=t>>5, co=t&31; g_wn1T[t] = wn1[co*64 + ci]; }
    for (int t=i0; t<32*64;   t+=stride){ int ci=t>>6, co=t&63; g_wn3T[t] = wn3[co*32 + ci]; }
}

// ---------------- offset conv: 27 <- 64, 3x3 pad1, leaky + sigmoid(ch>=18) ----------------
__global__ void __launch_bounds__(256) k_off(const float* __restrict__ x,
                                             const float* __restrict__ w,
                                             const float* __restrict__ bias){
    __shared__ float sh[64*102];  // [ci][3][34]
    int x0 = blockIdx.x*32, y = blockIdx.y, b = blockIdx.z;
    int tid = threadIdx.x;
    const float* xb = x + (size_t)b*Cn*HW;
    for (int e=tid; e<64*102; e+=256){
        int ci = e/102; int r = e%102; int dy = r/34; int xx = r%34;
        int gy = y+dy-1, gx = x0+xx-1;
        sh[e] = (gy>=0 && gy<Hn && gx>=0 && gx<Wn) ? xb[ci*HW + gy*Wn + gx] : 0.f;
    }
    __syncthreads();
    int pix = tid&31, g = tid>>5;
    for (int co=g; co<27; co+=8){
        float acc = __ldg(bias+co);
        const float* wc = w + co*576;
        #pragma unroll 4
        for (int ci=0; ci<64; ci++){
            const float* s = sh + ci*102 + pix;
            const float* wp = wc + ci*9;
            acc += s[0]*__ldg(wp+0) + s[1]*__ldg(wp+1) + s[2]*__ldg(wp+2)
                 + s[34]*__ldg(wp+3) + s[35]*__ldg(wp+4) + s[36]*__ldg(wp+5)
                 + s[68]*__ldg(wp+6) + s[69]*__ldg(wp+7) + s[70]*__ldg(wp+8);
        }
        float v = leakyf_(acc);
        if (co >= 18) v = sigmoidf_(v);
        g_om[((size_t)b*27+co)*HW + y*Wn + x0 + pix] = v;
    }
}

// ---------------- deformable conv: sample + 64 <- 576 matmul ----------------
__global__ void __launch_bounds__(256) k_deform(const float* __restrict__ x,
                                                const float* __restrict__ bias){
    __shared__ float val[576*16];       // [kc=ci*9+k][pix]
    __shared__ float cw[4][144];        // corner weights (incl validity*mask)
    __shared__ int   cidx[4][144];      // clamped linear HW indices
    int p0 = blockIdx.x*16;
    int b  = p0 / HW;
    int tid = threadIdx.x;
    if (tid < 144){
        int k = tid/16, pix = tid%16;
        int pp = (p0 + pix) % HW;
        int gy = pp / Wn, gx = pp % Wn;
        float dyv = g_om[((size_t)b*27 + 2*k  )*HW + pp];
        float dxv = g_om[((size_t)b*27 + 2*k+1)*HW + pp];
        float m   = g_om[((size_t)b*27 + 18+k )*HW + pp];
        float py = (float)gy + (float)(k/3 - 1) + dyv;
        float px = (float)gx + (float)(k%3 - 1) + dxv;
        float fy = floorf(py), fx = floorf(px);
        int y0 = (int)fy, xq = (int)fx;
        float wy = py - fy, wx = px - fx;
        int y1 = y0+1, x1 = xq+1;
        int yc0 = min(max(y0,0),Hn-1), yc1 = min(max(y1,0),Hn-1);
        int xc0 = min(max(xq,0),Wn-1), xc1 = min(max(x1,0),Wn-1);
        float vy0 = (y0>=0 && y0<Hn)?1.f:0.f;
        float vy1 = (y1>=0 && y1<Hn)?1.f:0.f;
        float vx0 = (xq>=0 && xq<Wn)?1.f:0.f;
        float vx1 = (x1>=0 && x1<Wn)?1.f:0.f;
        cw[0][tid] = (1.f-wy)*(1.f-wx)*vy0*vx0*m;  cidx[0][tid] = yc0*Wn+xc0;
        cw[1][tid] = (1.f-wy)*wx     *vy0*vx1*m;   cidx[1][tid] = yc0*Wn+xc1;
        cw[2][tid] = wy     *(1.f-wx)*vy1*vx0*m;   cidx[2][tid] = yc1*Wn+xc0;
        cw[3][tid] = wy     *wx      *vy1*vx1*m;   cidx[3][tid] = yc1*Wn+xc1;
    }
    __syncthreads();
    for (int t=tid; t<576*16; t+=256){
        int kci = t >> 4;            // ci*9+k
        int pix = t & 15;
        int ci = kci/9, k = kci - ci*9;
        int s = k*16+pix;
        const float* xb = x + ((size_t)b*Cn + ci)*HW;
        val[t] = cw[0][s]*__ldg(xb+cidx[0][s]) + cw[1][s]*__ldg(xb+cidx[1][s])
               + cw[2][s]*__ldg(xb+cidx[2][s]) + cw[3][s]*__ldg(xb+cidx[3][s]);
    }
    __syncthreads();
    int pix = tid & 15, g = tid >> 4;   // g in 0..15
    int co0 = g*4;
    float a0=0.f,a1=0.f,a2=0.f,a3=0.f;
    #pragma unroll 4
    for (int kc=0; kc<576; kc++){
        float v = val[kc*16 + pix];
        float4 wv = *(const float4*)&g_wdcT[kc*64 + co0];
        a0 += v*wv.x; a1 += v*wv.y; a2 += v*wv.z; a3 += v*wv.w;
    }
    int sp = (p0 + pix) % HW;
    float* out = g_xd + (size_t)b*Cn*HW + sp;
    out[(co0+0)*HW] = a0 + __ldg(bias+co0+0);
    out[(co0+1)*HW] = a1 + __ldg(bias+co0+1);
    out[(co0+2)*HW] = a2 + __ldg(bias+co0+2);
    out[(co0+3)*HW] = a3 + __ldg(bias+co0+3);
}

// ---------------- channel mean over H,W ----------------
__global__ void __launch_bounds__(256) k_mean(){
    int bc = blockIdx.x;   // 0..255
    const float* p = g_xd + (size_t)bc*HW;
    float s = 0.f;
    for (int i=threadIdx.x; i<HW; i+=256) s += p[i];
    __shared__ float red[256];
    red[threadIdx.x] = s; __syncthreads();
    for (int o=128; o>0; o>>=1){
        if (threadIdx.x < o) red[threadIdx.x] += red[threadIdx.x+o];
        __syncthreads();
    }
    if (threadIdx.x==0) g_mean[bc] = red[0]*(1.f/HW);
}

// ---------------- channel attention MLP ----------------
__global__ void k_ca(const float* __restrict__ w1, const float* __restrict__ b1,
                     const float* __restrict__ w2, const float* __restrict__ b2){
    int b = blockIdx.x; int t = threadIdx.x;   // 64 threads
    __shared__ float mn[64], h[8];
    mn[t] = g_mean[b*64+t];
    __syncthreads();
    if (t < 8){
        float s = __ldg(b1+t);
        for (int c=0;c<64;c++) s += __ldg(w1+t*64+c)*mn[c];
        h[t] = s > 0.f ? s : 0.f;
    }
    __syncthreads();
    float s = __ldg(b2+t);
    #pragma unroll
    for (int j=0;j<8;j++) s += __ldg(w2+t*8+j)*h[j];
    g_ca[b*64+t] = sigmoidf_(s);
}

// ---------------- spatial attention + xa = xd*(ca+sa) ----------------
__global__ void __launch_bounds__(256) k_saxa(const float* __restrict__ wsa,
                                              const float* __restrict__ bsa){
    __shared__ float sh[64*102];
    __shared__ float part[8][32];
    __shared__ float sav[32];
    int x0 = blockIdx.x*32, y = blockIdx.y, b = blockIdx.z;
    int tid = threadIdx.x;
    const float* xb = g_xd + (size_t)b*Cn*HW;
    for (int e=tid; e<64*102; e+=256){
        int ci = e/102; int r = e%102; int dy = r/34; int xx = r%34;
        int gy = y+dy-1, gx = x0+xx-1;
        sh[e] = (gy>=0 && gy<Hn && gx>=0 && gx<Wn) ? xb[ci*HW + gy*Wn + gx] : 0.f;
    }
    __syncthreads();
    int pix = tid&31, g = tid>>5;
    float acc = 0.f;
    for (int ci=g*8; ci<g*8+8; ci++){
        const float* s = sh + ci*102 + pix;
        const float* wp = wsa + ci*9;
        acc += s[0]*__ldg(wp+0) + s[1]*__ldg(wp+1) + s[2]*__ldg(wp+2)
             + s[34]*__ldg(wp+3) + s[35]*__ldg(wp+4) + s[36]*__ldg(wp+5)
             + s[68]*__ldg(wp+6) + s[69]*__ldg(wp+7) + s[70]*__ldg(wp+8);
    }
    part[g][pix] = acc;
    __syncthreads();
    if (g == 0){
        float t = __ldg(bsa);
        #pragma unroll
        for (int j=0;j<8;j++) t += part[j][pix];
        sav[pix] = sigmoidf_(t);
    }
    __syncthreads();
    float sa = sav[pix];
    for (int co=g; co<64; co+=8){
        float v = sh[co*102 + 34 + pix + 1];    // center tap
        g_xa[((size_t)b*64+co)*HW + y*Wn + x0 + pix] = v * (g_ca[b*64+co] + sa);
    }
}

// ---------------- r1: 1x1, 64 -> 256, leaky ----------------
__global__ void __launch_bounds__(256) k_r1(const float* __restrict__ bias){
    __shared__ float sh[64*32];
    int p0 = blockIdx.x*32; int b = p0/HW; int sp = p0%HW;
    int tid = threadIdx.x;
    for (int e=tid; e<64*32; e+=256){
        int ci=e>>5, pix=e&31;
        sh[e] = g_xa[((size_t)b*64+ci)*HW + sp + pix];
    }
    __syncthreads();
    int pix = tid&31, g = tid>>5;
    for (int cc=0; cc<4; cc++){
        int co0 = cc*64 + g*8;
        float acc[8];
        #pragma unroll
        for (int j=0;j<8;j++) acc[j] = __ldg(bias+co0+j);
        #pragma unroll 4
        for (int ci=0; ci<64; ci++){
            float v = sh[ci*32+pix];
            float4 wa = *(const float4*)&g_wr1T[ci*256+co0];
            float4 wb = *(const float4*)&g_wr1T[ci*256+co0+4];
            acc[0]+=v*wa.x; acc[1]+=v*wa.y; acc[2]+=v*wa.z; acc[3]+=v*wa.w;
            acc[4]+=v*wb.x; acc[5]+=v*wb.y; acc[6]+=v*wb.z; acc[7]+=v*wb.w;
        }
        #pragma unroll
        for (int j=0;j<8;j++)
            g_t1[((size_t)b*CM+co0+j)*HW + sp + pix] = leakyf_(acc[j]);
    }
}

// ---------------- r2: 3x3 pad1, 256 -> 64 (2 rows / block) ----------------
__global__ void __launch_bounds__(256) k_r2(const float* __restrict__ bias){
    __shared__ float sh[64*136];    // [ci][4 rows][34]
    int x0 = blockIdx.x*32;
    int y0 = blockIdx.y*2;
    int b  = blockIdx.z;
    int tid = threadIdx.x;
    int pix = tid&31, g = tid>>5;
    int co0 = g*8;
    float a0[8], a1[8];
    #pragma unroll
    for (int j=0;j<8;j++){ float bb = __ldg(bias+co0+j); a0[j]=bb; a1[j]=bb; }
    for (int cc=0; cc<4; cc++){
        __syncthreads();
        const float* tb = g_t1 + ((size_t)b*CM + cc*64)*HW;
        for (int e=tid; e<64*136; e+=256){
            int ci = e/136; int r = e%136; int dy = r/34; int xx = r%34;
            int gy = y0+dy-1, gx = x0+xx-1;
            sh[e] = (gy>=0 && gy<Hn && gx>=0 && gx<Wn) ? tb[ci*HW + gy*Wn + gx] : 0.f;
        }
        __syncthreads();
        const float* wb = g_wr2T + (size_t)cc*64*9*64;
        for (int ci=0; ci<64; ci++){
            const float* s  = sh + ci*136 + pix;
            const float* wp = wb + ci*9*64 + co0;
            #pragma unroll
            for (int k=0;k<9;k++){
                float v0 = s[(k/3)*34   + (k%3)];
                float v1 = s[(k/3+1)*34 + (k%3)];
                float4 wa = *(const float4*)(wp + k*64);
                float4 wc = *(const float4*)(wp + k*64 + 4);
                a0[0]+=v0*wa.x; a0[1]+=v0*wa.y; a0[2]+=v0*wa.z; a0[3]+=v0*wa.w;
                a0[4]+=v0*wc.x; a0[5]+=v0*wc.y; a0[6]+=v0*wc.z; a0[7]+=v0*wc.w;
                a1[0]+=v1*wa.x; a1[1]+=v1*wa.y; a1[2]+=v1*wa.z; a1[3]+=v1*wa.w;
                a1[4]+=v1*wc.x; a1[5]+=v1*wc.y; a1[6]+=v1*wc.z; a1[7]+=v1*wc.w;
            }
        }
    }
    #pragma unroll
    for (int j=0;j<8;j++){
        size_t o = ((size_t)b*64+co0+j)*HW;
        g_xr[o + y0*Wn     + x0+pix] = a0[j];
        g_xr[o + (y0+1)*Wn + x0+pix] = a1[j];
    }
}

// ---------------- n1: 1x1, 64 -> 32 ----------------
__global__ void __launch_bounds__(256) k_n1(const float* __restrict__ bias){
    __shared__ float sh[64*32];
    int p0 = blockIdx.x*32; int b = p0/HW; int sp = p0%HW;
    int tid = threadIdx.x;
    for (int e=tid; e<64*32; e+=256){
        int ci=e>>5, pix=e&31;
        sh[e] = g_xa[((size_t)b*64+ci)*HW + sp + pix];
    }
    __syncthreads();
    int pix = tid&31, g = tid>>5;
    int co0 = g*4;
    float acc[4];
    #pragma unroll
    for (int j=0;j<4;j++) acc[j] = __ldg(bias+co0+j);
    #pragma unroll 4
    for (int ci=0; ci<64; ci++){
        float v = sh[ci*32+pix];
        float4 wa = *(const float4*)&g_wn1T[ci*32+co0];
        acc[0]+=v*wa.x; acc[1]+=v*wa.y; acc[2]+=v*wa.z; acc[3]+=v*wa.w;
    }
    #pragma unroll
    for (int j=0;j<4;j++)
        g_n1[((size_t)b*CH+co0+j)*HW + sp + pix] = acc[j];
}

// ---------------- n2: depthwise 3x3 pad1 on 32 channels ----------------
__global__ void __launch_bounds__(256) k_n2(const float* __restrict__ w,
                                            const float* __restrict__ bias){
    int idx = blockIdx.x*256 + threadIdx.x;
    if (idx >= Bn*CH*HW) return;
    int pp = idx % HW; int bc = idx / HW; int c = bc % CH;
    int gy = pp/Wn, gx = pp%Wn;
    const float* in = g_n1 + (size_t)bc*HW;
    float acc = __ldg(bias+c);
    #pragma unroll
    for (int ky=0;ky<3;ky++){
        int yy = gy+ky-1;
        if (yy<0 || yy>=Hn) continue;
        #pragma unroll
        for (int kx=0;kx<3;kx++){
            int xx = gx+kx-1;
            if (xx<0 || xx>=Wn) continue;
            acc += in[yy*Wn+xx]*__ldg(w + c*9 + ky*3 + kx);
        }
    }
    g_n2[idx] = acc;
}

// ---------------- final: out = x + xr + (1x1 32->64)(n2) ----------------
__global__ void __launch_bounds__(256) k_final(const float* __restrict__ x,
                                               const float* __restrict__ bias,
                                               float* __restrict__ out){
    __shared__ float sh[32*32];
    int p0 = blockIdx.x*32; int b = p0/HW; int sp = p0%HW;
    int tid = threadIdx.x;
    for (int e=tid; e<32*32; e+=256){
        int ci=e>>5, pix=e&31;
        sh[e] = g_n2[((size_t)b*CH+ci)*HW + sp + pix];
    }
    __syncthreads();
    int pix = tid&31, g = tid>>5;
    int co0 = g*8;
    float acc[8];
    #pragma unroll
    for (int j=0;j<8;j++) acc[j] = __ldg(bias+co0+j);
    #pragma unroll 4
    for (int ci=0; ci<32; ci++){
        float v = sh[ci*32+pix];
        float4 wa = *(const float4*)&g_wn3T[ci*64+co0];
        float4 wb = *(const float4*)&g_wn3T[ci*64+co0+4];
        acc[0]+=v*wa.x; acc[1]+=v*wa.y; acc[2]+=v*wa.z; acc[3]+=v*wa.w;
        acc[4]+=v*wb.x; acc[5]+=v*wb.y; acc[6]+=v*wb.z; acc[7]+=v*wb.w;
    }
    #pragma unroll
    for (int j=0;j<8;j++){
        size_t o = ((size_t)b*64+co0+j)*HW + sp + pix;
        out[o] = x[o] + g_xr[o] + acc[j];
    }
}

// ---------------- launch ----------------
extern "C" void kernel_launch(void* const* d_in, const int* in_sizes, int n_in,
                              void* d_out, int out_size){
    const float* x     = (const float*)d_in[0];
    const float* w_off = (const float*)d_in[1];
    const float* b_off = (const float*)d_in[2];
    const float* w_dc  = (const float*)d_in[3];
    const float* b_dc  = (const float*)d_in[4];
    const float* w_ca1 = (const float*)d_in[5];
    const float* b_ca1 = (const float*)d_in[6];
    const float* w_ca2 = (const float*)d_in[7];
    const float* b_ca2 = (const float*)d_in[8];
    const float* w_sa  = (const float*)d_in[9];
    const float* b_sa  = (const float*)d_in[10];
    const float* w_r1  = (const float*)d_in[11];
    const float* b_r1  = (const float*)d_in[12];
    const float* w_r2  = (const float*)d_in[13];
    const float* b_r2  = (const float*)d_in[14];
    const float* w_n1  = (const float*)d_in[15];
    const float* b_n1  = (const float*)d_in[16];
    const float* w_n2  = (const float*)d_in[17];
    const float* b_n2  = (const float*)d_in[18];
    const float* w_n3  = (const float*)d_in[19];
    const float* b_n3  = (const float*)d_in[20];
    float* out = (float*)d_out;

    k_prep<<<256, 256>>>(w_dc, w_r2, w_r1, w_n1, w_n3);
    k_off<<<dim3(Wn/32, Hn, Bn), 256>>>(x, w_off, b_off);
    k_deform<<<(Bn*HW)/16, 256>>>(x, b_dc);
    k_mean<<<Bn*Cn, 256>>>();
    k_ca<<<Bn, 64>>>(w_ca1, b_ca1, w_ca2, b_ca2);
    k_saxa<<<dim3(Wn/32, Hn, Bn), 256>>>(w_sa, b_sa);
    k_r1<<<(Bn*HW)/32, 256>>>(b_r1);
    k_r2<<<dim3(Wn/32, Hn/2, Bn), 256>>>(b_r2);
    k_n1<<<(Bn*HW)/32, 256>>>(b_n1);
    k_n2<<<(Bn*CH*HW + 255)/256, 256>>>(w_n2, b_n2);
    k_final<<<(Bn*HW)/32, 256>>>(x, b_n3, out);
}

// round 5
// speedup vs baseline: 1.4996x; 1.4996x over previous
#include <cuda_runtime.h>
#include <math.h>
#include <stdint.h>

#define Bn 4
#define Cn 64
#define Hn 192
#define Wn 192
#define HW (Hn*Wn)      // 36864
#define CM 256          // C*EXP
#define CH 32           // C/2

// ---------------- scratch (static device globals; no allocation) ----------------
__device__ float g_om  [Bn*27*HW];
__device__ float g_xd  [Bn*Cn*HW];
__device__ float g_mean[Bn*Cn];
__device__ float g_ca  [Bn*Cn];
__device__ float g_xa  [Bn*Cn*HW];
__device__ float g_t1  [Bn*CM*HW];
__device__ float g_xr  [Bn*Cn*HW];
__device__ float g_n1  [Bn*CH*HW];
__device__ float g_n2  [Bn*CH*HW];
// transposed weights
__device__ __align__(16) float g_wdcT[576*64];     // [kc][co]
__device__ __align__(16) float g_wr2T[64*2304];    // [co][tap*256+cin], tf32-rounded
__device__ __align__(16) float g_wr1T[64*256];     // [ci][co]
__device__ __align__(16) float g_wn1T[64*32];
__device__ __align__(16) float g_wn3T[32*64];

__device__ __forceinline__ float sigmoidf_(float v){ return 1.f/(1.f+expf(-v)); }
__device__ __forceinline__ float leakyf_(float v){ return v >= 0.f ? v : 0.1f*v; }
__device__ __forceinline__ float to_tf32(float v){
    uint32_t r; asm("cvt.rna.tf32.f32 %0, %1;" : "=r"(r) : "f"(v));
    return __uint_as_float(r);
}
__device__ __forceinline__ void mma_tf32(float* c, const uint32_t* a, const uint32_t* b){
    asm volatile("mma.sync.aligned.m16n8k8.row.col.f32.tf32.tf32.f32 "
        "{%0,%1,%2,%3}, {%4,%5,%6,%7}, {%8,%9}, {%0,%1,%2,%3};"
        : "+f"(c[0]), "+f"(c[1]), "+f"(c[2]), "+f"(c[3])
        : "r"(a[0]), "r"(a[1]), "r"(a[2]), "r"(a[3]), "r"(b[0]), "r"(b[1]));
}

// ---------------- weight transposes ----------------
__global__ void k_prep(const float* __restrict__ wdc, const float* __restrict__ wr2,
                       const float* __restrict__ wr1, const float* __restrict__ wn1,
                       const float* __restrict__ wn3){
    int stride = gridDim.x*blockDim.x;
    int i0 = blockIdx.x*blockDim.x + threadIdx.x;
    for (int t=i0; t<576*64;  t+=stride){ int kc=t>>6, co=t&63; g_wdcT[t] = wdc[co*576 + kc]; }
    for (int t=i0; t<64*2304; t+=stride){
        int co = t/2304; int r = t - co*2304; int tap = r>>8; int cin = r&255;
        g_wr2T[t] = to_tf32(wr2[co*2304 + cin*9 + tap]);
    }
    for (int t=i0; t<64*256;  t+=stride){ int ci=t>>8, co=t&255; g_wr1T[t] = wr1[co*64 + ci]; }
    for (int t=i0; t<64*32;   t+=stride){ int ci=t>>5, co=t&31; g_wn1T[t] = wn1[co*64 + ci]; }
    for (int t=i0; t<32*64;   t+=stride){ int ci=t>>6, co=t&63; g_wn3T[t] = wn3[co*32 + ci]; }
}

// ---------------- offset conv: 27 <- 64, 3x3 pad1, leaky + sigmoid(ch>=18) ----------------
__global__ void __launch_bounds__(256) k_off(const float* __restrict__ x,
                                             const float* __restrict__ w,
                                             const float* __restrict__ bias){
    __shared__ float sh[64*102];  // [ci][3][34]
    int x0 = blockIdx.x*32, y = blockIdx.y, b = blockIdx.z;
    int tid = threadIdx.x;
    const float* xb = x + (size_t)b*Cn*HW;
    for (int e=tid; e<64*102; e+=256){
        int ci = e/102; int r = e%102; int dy = r/34; int xx = r%34;
        int gy = y+dy-1, gx = x0+xx-1;
        sh[e] = (gy>=0 && gy<Hn && gx>=0 && gx<Wn) ? xb[ci*HW + gy*Wn + gx] : 0.f;
    }
    __syncthreads();
    int pix = tid&31, g = tid>>5;
    for (int co=g; co<27; co+=8){
        float acc = __ldg(bias+co);
        const float* wc = w + co*576;
        #pragma unroll 4
        for (int ci=0; ci<64; ci++){
            const float* s = sh + ci*102 + pix;
            const float* wp = wc + ci*9;
            acc += s[0]*__ldg(wp+0) + s[1]*__ldg(wp+1) + s[2]*__ldg(wp+2)
                 + s[34]*__ldg(wp+3) + s[35]*__ldg(wp+4) + s[36]*__ldg(wp+5)
                 + s[68]*__ldg(wp+6) + s[69]*__ldg(wp+7) + s[70]*__ldg(wp+8);
        }
        float v = leakyf_(acc);
        if (co >= 18) v = sigmoidf_(v);
        g_om[((size_t)b*27+co)*HW + y*Wn + x0 + pix] = v;
    }
}

// ---------------- deformable conv: sample + 64 <- 576 matmul ----------------
__global__ void __launch_bounds__(256) k_deform(const float* __restrict__ x,
                                                const float* __restrict__ bias){
    __shared__ float val[576*16];
    __shared__ float cw[4][144];
    __shared__ int   cidx[4][144];
    int p0 = blockIdx.x*16;
    int b  = p0 / HW;
    int tid = threadIdx.x;
    if (tid < 144){
        int k = tid/16, pix = tid%16;
        int pp = (p0 + pix) % HW;
        int gy = pp / Wn, gx = pp % Wn;
        float dyv = g_om[((size_t)b*27 + 2*k  )*HW + pp];
        float dxv = g_om[((size_t)b*27 + 2*k+1)*HW + pp];
        float m   = g_om[((size_t)b*27 + 18+k )*HW + pp];
        float py = (float)gy + (float)(k/3 - 1) + dyv;
        float px = (float)gx + (float)(k%3 - 1) + dxv;
        float fy = floorf(py), fx = floorf(px);
        int y0 = (int)fy, xq = (int)fx;
        float wy = py - fy, wx = px - fx;
        int y1 = y0+1, x1 = xq+1;
        int yc0 = min(max(y0,0),Hn-1), yc1 = min(max(y1,0),Hn-1);
        int xc0 = min(max(xq,0),Wn-1), xc1 = min(max(x1,0),Wn-1);
        float vy0 = (y0>=0 && y0<Hn)?1.f:0.f;
        float vy1 = (y1>=0 && y1<Hn)?1.f:0.f;
        float vx0 = (xq>=0 && xq<Wn)?1.f:0.f;
        float vx1 = (x1>=0 && x1<Wn)?1.f:0.f;
        cw[0][tid] = (1.f-wy)*(1.f-wx)*vy0*vx0*m;  cidx[0][tid] = yc0*Wn+xc0;
        cw[1][tid] = (1.f-wy)*wx     *vy0*vx1*m;   cidx[1][tid] = yc0*Wn+xc1;
        cw[2][tid] = wy     *(1.f-wx)*vy1*vx0*m;   cidx[2][tid] = yc1*Wn+xc0;
        cw[3][tid] = wy     *wx      *vy1*vx1*m;   cidx[3][tid] = yc1*Wn+xc1;
    }
    __syncthreads();
    for (int t=tid; t<576*16; t+=256){
        int kci = t >> 4;
        int pix = t & 15;
        int ci = kci/9, k = kci - ci*9;
        int s = k*16+pix;
        const float* xb = x + ((size_t)b*Cn + ci)*HW;
        val[t] = cw[0][s]*__ldg(xb+cidx[0][s]) + cw[1][s]*__ldg(xb+cidx[1][s])
               + cw[2][s]*__ldg(xb+cidx[2][s]) + cw[3][s]*__ldg(xb+cidx[3][s]);
    }
    __syncthreads();
    int pix = tid & 15, g = tid >> 4;
    int co0 = g*4;
    float a0=0.f,a1=0.f,a2=0.f,a3=0.f;
    #pragma unroll 4
    for (int kc=0; kc<576; kc++){
        float v = val[kc*16 + pix];
        float4 wv = *(const float4*)&g_wdcT[kc*64 + co0];
        a0 += v*wv.x; a1 += v*wv.y; a2 += v*wv.z; a3 += v*wv.w;
    }
    int sp = (p0 + pix) % HW;
    float* out = g_xd + (size_t)b*Cn*HW + sp;
    out[(co0+0)*HW] = a0 + __ldg(bias+co0+0);
    out[(co0+1)*HW] = a1 + __ldg(bias+co0+1);
    out[(co0+2)*HW] = a2 + __ldg(bias+co0+2);
    out[(co0+3)*HW] = a3 + __ldg(bias+co0+3);
}

// ---------------- channel mean over H,W ----------------
__global__ void __launch_bounds__(256) k_mean(){
    int bc = blockIdx.x;
    const float* p = g_xd + (size_t)bc*HW;
    float s = 0.f;
    for (int i=threadIdx.x; i<HW; i+=256) s += p[i];
    __shared__ float red[256];
    red[threadIdx.x] = s; __syncthreads();
    for (int o=128; o>0; o>>=1){
        if (threadIdx.x < o) red[threadIdx.x] += red[threadIdx.x+o];
        __syncthreads();
    }
    if (threadIdx.x==0) g_mean[bc] = red[0]*(1.f/HW);
}

// ---------------- channel attention MLP ----------------
__global__ void k_ca(const float* __restrict__ w1, const float* __restrict__ b1,
                     const float* __restrict__ w2, const float* __restrict__ b2){
    int b = blockIdx.x; int t = threadIdx.x;
    __shared__ float mn[64], h[8];
    mn[t] = g_mean[b*64+t];
    __syncthreads();
    if (t < 8){
        float s = __ldg(b1+t);
        for (int c=0;c<64;c++) s += __ldg(w1+t*64+c)*mn[c];
        h[t] = s > 0.f ? s : 0.f;
    }
    __syncthreads();
    float s = __ldg(b2+t);
    #pragma unroll
    for (int j=0;j<8;j++) s += __ldg(w2+t*8+j)*h[j];
    g_ca[b*64+t] = sigmoidf_(s);
}

// ---------------- spatial attention + xa = xd*(ca+sa) ----------------
__global__ void __launch_bounds__(256) k_saxa(const float* __restrict__ wsa,
                                              const float* __restrict__ bsa){
    __shared__ float sh[64*102];
    __shared__ float part[8][32];
    __shared__ float sav[32];
    int x0 = blockIdx.x*32, y = blockIdx.y, b = blockIdx.z;
    int tid = threadIdx.x;
    const float* xb = g_xd + (size_t)b*Cn*HW;
    for (int e=tid; e<64*102; e+=256){
        int ci = e/102; int r = e%102; int dy = r/34; int xx = r%34;
        int gy = y+dy-1, gx = x0+xx-1;
        sh[e] = (gy>=0 && gy<Hn && gx>=0 && gx<Wn) ? xb[ci*HW + gy*Wn + gx] : 0.f;
    }
    __syncthreads();
    int pix = tid&31, g = tid>>5;
    float acc = 0.f;
    for (int ci=g*8; ci<g*8+8; ci++){
        const float* s = sh + ci*102 + pix;
        const float* wp = wsa + ci*9;
        acc += s[0]*__ldg(wp+0) + s[1]*__ldg(wp+1) + s[2]*__ldg(wp+2)
             + s[34]*__ldg(wp+3) + s[35]*__ldg(wp+4) + s[36]*__ldg(wp+5)
             + s[68]*__ldg(wp+6) + s[69]*__ldg(wp+7) + s[70]*__ldg(wp+8);
    }
    part[g][pix] = acc;
    __syncthreads();
    if (g == 0){
        float t = __ldg(bsa);
        #pragma unroll
        for (int j=0;j<8;j++) t += part[j][pix];
        sav[pix] = sigmoidf_(t);
    }
    __syncthreads();
    float sa = sav[pix];
    for (int co=g; co<64; co+=8){
        float v = sh[co*102 + 34 + pix + 1];
        g_xa[((size_t)b*64+co)*HW + y*Wn + x0 + pix] = v * (g_ca[b*64+co] + sa);
    }
}

// ---------------- r1: 1x1, 64 -> 256, leaky, output rounded to tf32 ----------------
__global__ void __launch_bounds__(256) k_r1(const float* __restrict__ bias){
    __shared__ float sh[64*32];
    int p0 = blockIdx.x*32; int b = p0/HW; int sp = p0%HW;
    int tid = threadIdx.x;
    for (int e=tid; e<64*32; e+=256){
        int ci=e>>5, pix=e&31;
        sh[e] = g_xa[((size_t)b*64+ci)*HW + sp + pix];
    }
    __syncthreads();
    int pix = tid&31, g = tid>>5;
    for (int cc=0; cc<4; cc++){
        int co0 = cc*64 + g*8;
        float acc[8];
        #pragma unroll
        for (int j=0;j<8;j++) acc[j] = __ldg(bias+co0+j);
        #pragma unroll 4
        for (int ci=0; ci<64; ci++){
            float v = sh[ci*32+pix];
            float4 wa = *(const float4*)&g_wr1T[ci*256+co0];
            float4 wb = *(const float4*)&g_wr1T[ci*256+co0+4];
            acc[0]+=v*wa.x; acc[1]+=v*wa.y; acc[2]+=v*wa.z; acc[3]+=v*wa.w;
            acc[4]+=v*wb.x; acc[5]+=v*wb.y; acc[6]+=v*wb.z; acc[7]+=v*wb.w;
        }
        #pragma unroll
        for (int j=0;j<8;j++)
            g_t1[((size_t)b*CM+co0+j)*HW + sp + pix] = to_tf32(leakyf_(acc[j]));
    }
}

// ---------------- r2 via mma.sync tf32: D[128pix,64co] = A[128,2304] x W[64,2304]^T ----------------
// K ordering: k = tap*256 + cin. 72 chunks of Kc=32 (fixed tap, 32 cins).
// Warp grid 4x2 (m32 x n32). Fragments per PTX m16n8k8 row.col layout.
__global__ void __launch_bounds__(256) k_r2mma(const float* __restrict__ bias){
    __shared__ __align__(16) float As[128*36];   // [pixel][k], pad 36
    __shared__ __align__(16) float Bs[64*36];    // [cout][k],  pad 36

    int tile = blockIdx.x;                 // 0..1151
    int b  = tile / 288;
    int p0 = (tile - b*288) * 128;
    int tid = threadIdx.x;
    int lane = tid & 31;
    int warp = tid >> 5;
    int m0 = (warp & 3) * 32;              // pixel-row base for this warp
    int n0 = (warp >> 2) * 32;             // cout base
    int g = lane >> 2, t = lane & 3;

    const float* t1b = g_t1 + (size_t)b*CM*HW;
    const uint32_t* Asu = (const uint32_t*)As;
    const uint32_t* Bsu = (const uint32_t*)Bs;

    float acc[2][4][4];
    #pragma unroll
    for (int mi=0;mi<2;mi++)
        #pragma unroll
        for (int ni=0;ni<4;ni++)
            #pragma unroll
            for (int j=0;j<4;j++) acc[mi][ni][j] = 0.f;

    for (int j = 0; j < 72; j++){
        int tap = j >> 3;
        int cb  = (j & 7) * 32;
        int ty = tap/3 - 1, tx = tap - (tap/3)*3 - 1;
        int off = ty*Wn + tx;
        __syncthreads();
        // ---- stage A: 128 pixels x 32 k (4 channels per float4, strided loads) ----
        #pragma unroll
        for (int it = 0; it < 4; it++){
            int id = tid + it*256;
            int p  = id & 127;
            int j4 = id >> 7;          // 0..7
            int q  = p0 + p;
            int qy = q / Wn;
            int qx = q - qy*Wn;
            int sy = qy + ty, sx = qx + tx;
            float4 v = make_float4(0.f, 0.f, 0.f, 0.f);
            if ((unsigned)sy < (unsigned)Hn && (unsigned)sx < (unsigned)Wn){
                const float* src = t1b + (size_t)(cb + j4*4)*HW + q + off;
                v.x = __ldg(src);
                v.y = __ldg(src + HW);
                v.z = __ldg(src + 2*HW);
                v.w = __ldg(src + 3*HW);
            }
            *(float4*)&As[p*36 + j4*4] = v;
        }
        // ---- stage B: 64 couts x 32 k ----
        const float* wsrc = g_wr2T + tap*256 + cb;
        #pragma unroll
        for (int it = 0; it < 2; it++){
            int id = tid + it*256;
            int f4 = id & 7;
            int co = id >> 3;
            float4 wv = *(const float4*)(wsrc + co*2304 + f4*4);
            *(float4*)&Bs[co*36 + f4*4] = wv;
        }
        __syncthreads();
        // ---- compute: 4 k-steps of k8 ----
        #pragma unroll
        for (int kk = 0; kk < 4; kk++){
            int k0 = kk*8;
            uint32_t afr[2][4], bfr[4][2];
            #pragma unroll
            for (int mi=0;mi<2;mi++){
                int r = m0 + mi*16;
                afr[mi][0] = Asu[(r+g  )*36 + k0 + t];
                afr[mi][1] = Asu[(r+g+8)*36 + k0 + t];
                afr[mi][2] = Asu[(r+g  )*36 + k0 + t + 4];
                afr[mi][3] = Asu[(r+g+8)*36 + k0 + t + 4];
            }
            #pragma unroll
            for (int ni=0;ni<4;ni++){
                int cN = n0 + ni*8 + g;
                bfr[ni][0] = Bsu[cN*36 + k0 + t];
                bfr[ni][1] = Bsu[cN*36 + k0 + t + 4];
            }
            #pragma unroll
            for (int mi=0;mi<2;mi++)
                #pragma unroll
                for (int ni=0;ni<4;ni++)
                    mma_tf32(acc[mi][ni], afr[mi], bfr[ni]);
        }
    }
    // ---- epilogue: scatter D + bias to g_xr ----
    float* xrb = g_xr + (size_t)b*Cn*HW + p0;
    #pragma unroll
    for (int mi=0;mi<2;mi++){
        int row = m0 + mi*16 + g;
        #pragma unroll
        for (int ni=0;ni<4;ni++){
            int col = n0 + ni*8 + 2*t;
            float b0 = __ldg(bias + col), b1 = __ldg(bias + col + 1);
            xrb[(size_t)col*HW     + row    ] = acc[mi][ni][0] + b0;
            xrb[(size_t)(col+1)*HW + row    ] = acc[mi][ni][1] + b1;
            xrb[(size_t)col*HW     + row + 8] = acc[mi][ni][2] + b0;
            xrb[(size_t)(col+1)*HW + row + 8] = acc[mi][ni][3] + b1;
        }
    }
}

// ---------------- n1: 1x1, 64 -> 32 ----------------
__global__ void __launch_bounds__(256) k_n1(const float* __restrict__ bias){
    __shared__ float sh[64*32];
    int p0 = blockIdx.x*32; int b = p0/HW; int sp = p0%HW;
    int tid = threadIdx.x;
    for (int e=tid; e<64*32; e+=256){
        int ci=e>>5, pix=e&31;
        sh[e] = g_xa[((size_t)b*64+ci)*HW + sp + pix];
    }
    __syncthreads();
    int pix = tid&31, g = tid>>5;
    int co0 = g*4;
    float acc[4];
    #pragma unroll
    for (int j=0;j<4;j++) acc[j] = __ldg(bias+co0+j);
    #pragma unroll 4
    for (int ci=0; ci<64; ci++){
        float v = sh[ci*32+pix];
        float4 wa = *(const float4*)&g_wn1T[ci*32+co0];
        acc[0]+=v*wa.x; acc[1]+=v*wa.y; acc[2]+=v*wa.z; acc[3]+=v*wa.w;
    }
    #pragma unroll
    for (int j=0;j<4;j++)
        g_n1[((size_t)b*CH+co0+j)*HW + sp + pix] = acc[j];
}

// ---------------- n2: depthwise 3x3 pad1 on 32 channels ----------------
__global__ void __launch_bounds__(256) k_n2(const float* __restrict__ w,
                                            const float* __restrict__ bias){
    int idx = blockIdx.x*256 + threadIdx.x;
    if (idx >= Bn*CH*HW) return;
    int pp = idx % HW; int bc = idx / HW; int c = bc % CH;
    int gy = pp/Wn, gx = pp%Wn;
    const float* in = g_n1 + (size_t)bc*HW;
    float acc = __ldg(bias+c);
    #pragma unroll
    for (int ky=0;ky<3;ky++){
        int yy = gy+ky-1;
        if (yy<0 || yy>=Hn) continue;
        #pragma unroll
        for (int kx=0;kx<3;kx++){
            int xx = gx+kx-1;
            if (xx<0 || xx>=Wn) continue;
            acc += in[yy*Wn+xx]*__ldg(w + c*9 + ky*3 + kx);
        }
    }
    g_n2[idx] = acc;
}

// ---------------- final: out = x + xr + (1x1 32->64)(n2) ----------------
__global__ void __launch_bounds__(256) k_final(const float* __restrict__ x,
                                               const float* __restrict__ bias,
                                               float* __restrict__ out){
    __shared__ float sh[32*32];
    int p0 = blockIdx.x*32; int b = p0/HW; int sp = p0%HW;
    int tid = threadIdx.x;
    for (int e=tid; e<32*32; e+=256){
        int ci=e>>5, pix=e&31;
        sh[e] = g_n2[((size_t)b*CH+ci)*HW + sp + pix];
    }
    __syncthreads();
    int pix = tid&31, g = tid>>5;
    int co0 = g*8;
    float acc[8];
    #pragma unroll
    for (int j=0;j<8;j++) acc[j] = __ldg(bias+co0+j);
    #pragma unroll 4
    for (int ci=0; ci<32; ci++){
        float v = sh[ci*32+pix];
        float4 wa = *(const float4*)&g_wn3T[ci*64+co0];
        float4 wb = *(const float4*)&g_wn3T[ci*64+co0+4];
        acc[0]+=v*wa.x; acc[1]+=v*wa.y; acc[2]+=v*wa.z; acc[3]+=v*wa.w;
        acc[4]+=v*wb.x; acc[5]+=v*wb.y; acc[6]+=v*wb.z; acc[7]+=v*wb.w;
    }
    #pragma unroll
    for (int j=0;j<8;j++){
        size_t o = ((size_t)b*64+co0+j)*HW + sp + pix;
        out[o] = x[o] + g_xr[o] + acc[j];
    }
}

// ---------------- launch ----------------
extern "C" void kernel_launch(void* const* d_in, const int* in_sizes, int n_in,
                              void* d_out, int out_size){
    const float* x     = (const float*)d_in[0];
    const float* w_off = (const float*)d_in[1];
    const float* b_off = (const float*)d_in[2];
    const float* w_dc  = (const float*)d_in[3];
    const float* b_dc  = (const float*)d_in[4];
    const float* w_ca1 = (const float*)d_in[5];
    const float* b_ca1 = (const float*)d_in[6];
    const float* w_ca2 = (const float*)d_in[7];
    const float* b_ca2 = (const float*)d_in[8];
    const float* w_sa  = (const float*)d_in[9];
    const float* b_sa  = (const float*)d_in[10];
    const float* w_r1  = (const float*)d_in[11];
    const float* b_r1  = (const float*)d_in[12];
    const float* w_r2  = (const float*)d_in[13];
    const float* b_r2  = (const float*)d_in[14];
    const float* w_n1  = (const float*)d_in[15];
    const float* b_n1  = (const float*)d_in[16];
    const float* w_n2  = (const float*)d_in[17];
    const float* b_n2  = (const float*)d_in[18];
    const float* w_n3  = (const float*)d_in[19];
    const float* b_n3  = (const float*)d_in[20];
    float* out = (float*)d_out;

    k_prep<<<256, 256>>>(w_dc, w_r2, w_r1, w_n1, w_n3);
    k_off<<<dim3(Wn/32, Hn, Bn), 256>>>(x, w_off, b_off);
    k_deform<<<(Bn*HW)/16, 256>>>(x, b_dc);
    k_mean<<<Bn*Cn, 256>>>();
    k_ca<<<Bn, 64>>>(w_ca1, b_ca1, w_ca2, b_ca2);
    k_saxa<<<dim3(Wn/32, Hn, Bn), 256>>>(w_sa, b_sa);
    k_r1<<<(Bn*HW)/32, 256>>>(b_r1);
    k_r2mma<<<1152, 256>>>(b_r2);
    k_n1<<<(Bn*HW)/32, 256>>>(b_n1);
    k_n2<<<(Bn*CH*HW + 255)/256, 256>>>(w_n2, b_n2);
    k_final<<<(Bn*HW)/32, 256>>>(x, b_n3, out);
}

// round 6
// speedup vs baseline: 3.3628x; 2.2425x over previous
#include <cuda_runtime.h>
#include <math.h>
#include <stdint.h>

#define Bn 4
#define Cn 64
#define Hn 192
#define Wn 192
#define HW (Hn*Wn)      // 36864
#define CM 256          // C*EXP
#define CH 32           // C/2

// ---------------- scratch (static device globals; no allocation) ----------------
__device__ float g_om  [Bn*27*HW];
__device__ float g_xd  [Bn*Cn*HW];
__device__ float g_mean[Bn*Cn];
__device__ float g_ca  [Bn*Cn];
__device__ float g_xa  [Bn*Cn*HW];
__device__ float g_t1  [Bn*CM*HW];
__device__ float g_xr  [Bn*Cn*HW];
__device__ float g_n1  [Bn*CH*HW];
__device__ float g_n2  [Bn*CH*HW];
// transposed weights (tf32-rounded where used by MMA)
__device__ __align__(16) float g_woffT[32*576];    // [co(pad32)][tap*64+ci]
__device__ __align__(16) float g_wdcT2[64*576];    // [co][tap*64+ci]
__device__ __align__(16) float g_wr1T2[256*64];    // [co][ci]
__device__ __align__(16) float g_wr2T[64*2304];    // [co][tap*256+cin]
__device__ __align__(16) float g_wn1T[64*32];
__device__ __align__(16) float g_wn3T[32*64];

__device__ __forceinline__ float sigmoidf_(float v){ return 1.f/(1.f+expf(-v)); }
__device__ __forceinline__ float leakyf_(float v){ return v >= 0.f ? v : 0.1f*v; }
__device__ __forceinline__ float to_tf32(float v){
    uint32_t r; asm("cvt.rna.tf32.f32 %0, %1;" : "=r"(r) : "f"(v));
    return __uint_as_float(r);
}
__device__ __forceinline__ void mma_tf32(float* c, const uint32_t* a, const uint32_t* b){
    asm volatile("mma.sync.aligned.m16n8k8.row.col.f32.tf32.tf32.f32 "
        "{%0,%1,%2,%3}, {%4,%5,%6,%7}, {%8,%9}, {%0,%1,%2,%3};"
        : "+f"(c[0]), "+f"(c[1]), "+f"(c[2]), "+f"(c[3])
        : "r"(a[0]), "r"(a[1]), "r"(a[2]), "r"(a[3]), "r"(b[0]), "r"(b[1]));
}

// ---------------- weight transposes ----------------
__global__ void k_prep(const float* __restrict__ woff, const float* __restrict__ wdc,
                       const float* __restrict__ wr2,  const float* __restrict__ wr1,
                       const float* __restrict__ wn1,  const float* __restrict__ wn3){
    int stride = gridDim.x*blockDim.x;
    int i0 = blockIdx.x*blockDim.x + threadIdx.x;
    for (int t=i0; t<32*576; t+=stride){
        int co = t/576; int r = t - co*576; int tap = r>>6; int ci = r&63;
        g_woffT[t] = (co < 27) ? to_tf32(woff[co*576 + ci*9 + tap]) : 0.f;
    }
    for (int t=i0; t<64*576; t+=stride){
        int co = t/576; int r = t - co*576; int tap = r>>6; int ci = r&63;
        g_wdcT2[t] = to_tf32(wdc[co*576 + ci*9 + tap]);
    }
    for (int t=i0; t<64*2304; t+=stride){
        int co = t/2304; int r = t - co*2304; int tap = r>>8; int cin = r&255;
        g_wr2T[t] = to_tf32(wr2[co*2304 + cin*9 + tap]);
    }
    for (int t=i0; t<256*64; t+=stride){ g_wr1T2[t] = to_tf32(wr1[t]); }
    for (int t=i0; t<64*32;  t+=stride){ int ci=t>>5, co=t&31; g_wn1T[t] = wn1[co*64 + ci]; }
    for (int t=i0; t<32*64;  t+=stride){ int ci=t>>6, co=t&63; g_wn3T[t] = wn3[co*32 + ci]; }
}

// ---------------- offset conv via mma: 27(pad32) <- 64x3x3, leaky + sigmoid(>=18) ----------------
__global__ void __launch_bounds__(256) k_offmma(const float* __restrict__ x,
                                                const float* __restrict__ bias){
    __shared__ __align__(16) float As[128*36];
    __shared__ __align__(16) float Bs[32*36];
    int tile = blockIdx.x;
    int b  = tile / 288;
    int pp0 = (tile - b*288) * 128;
    int tid = threadIdx.x;
    int lane = tid & 31;
    int warp = tid >> 5;
    int m0 = warp * 16;                    // 8 warps cover m=128
    int g = lane >> 2, t = lane & 3;

    const float* xb = x + (size_t)b*Cn*HW;
    const uint32_t* Asu = (const uint32_t*)As;
    const uint32_t* Bsu = (const uint32_t*)Bs;

    float acc[4][4];
    #pragma unroll
    for (int ni=0;ni<4;ni++)
        #pragma unroll
        for (int j=0;j<4;j++) acc[ni][j] = 0.f;

    for (int j = 0; j < 18; j++){
        int tap = j >> 1;
        int ci0 = (j & 1) * 32;
        int ty = tap/3 - 1, tx = tap - (tap/3)*3 - 1;
        int off = ty*Wn + tx;
        __syncthreads();
        // stage A (border-checked taps from x, tf32-rounded)
        #pragma unroll
        for (int it = 0; it < 4; it++){
            int id = tid + it*256;
            int pix = id & 127;
            int j4  = id >> 7;
            int q  = pp0 + pix;
            int qy = q / Wn;
            int qx = q - qy*Wn;
            int sy = qy + ty, sx = qx + tx;
            float4 v = make_float4(0.f,0.f,0.f,0.f);
            if ((unsigned)sy < (unsigned)Hn && (unsigned)sx < (unsigned)Wn){
                const float* src = xb + (size_t)(ci0 + j4*4)*HW + q + off;
                v.x = to_tf32(__ldg(src));
                v.y = to_tf32(__ldg(src + HW));
                v.z = to_tf32(__ldg(src + 2*HW));
                v.w = to_tf32(__ldg(src + 3*HW));
            }
            *(float4*)&As[pix*36 + j4*4] = v;
        }
        // stage B: 32 rows x 8 float4 = 256 tasks
        {
            int f4 = tid & 7;
            int co = tid >> 3;
            float4 wv = *(const float4*)(g_woffT + co*576 + tap*64 + ci0 + f4*4);
            *(float4*)&Bs[co*36 + f4*4] = wv;
        }
        __syncthreads();
        #pragma unroll
        for (int kk = 0; kk < 4; kk++){
            int k0 = kk*8;
            uint32_t afr[4], bfr[4][2];
            afr[0] = Asu[(m0+g  )*36 + k0 + t];
            afr[1] = Asu[(m0+g+8)*36 + k0 + t];
            afr[2] = Asu[(m0+g  )*36 + k0 + t + 4];
            afr[3] = Asu[(m0+g+8)*36 + k0 + t + 4];
            #pragma unroll
            for (int ni=0;ni<4;ni++){
                int cN = ni*8 + g;
                bfr[ni][0] = Bsu[cN*36 + k0 + t];
                bfr[ni][1] = Bsu[cN*36 + k0 + t + 4];
            }
            #pragma unroll
            for (int ni=0;ni<4;ni++)
                mma_tf32(acc[ni], afr, bfr[ni]);
        }
    }
    // epilogue: leaky all, sigmoid ch>=18, store channels <27
    float* omb = g_om + (size_t)b*27*HW + pp0;
    #pragma unroll
    for (int ni=0;ni<4;ni++){
        int col = ni*8 + 2*t;
        #pragma unroll
        for (int u=0;u<2;u++){
            int c = col + u;
            if (c < 27){
                float bb = __ldg(bias + c);
                #pragma unroll
                for (int mi=0;mi<2;mi++){
                    int row = m0 + g + mi*8;
                    float v = leakyf_(acc[ni][mi*2+u] + bb);
                    if (c >= 18) v = sigmoidf_(v);
                    omb[(size_t)c*HW + row] = v;
                }
            }
        }
    }
}

// ---------------- deformable conv via mma: gather + D[128,64] = V[128,576] x W[64,576]^T ----------------
__global__ void __launch_bounds__(256) k_deform_mma(const float* __restrict__ x,
                                                    const float* __restrict__ bias){
    __shared__ __align__(16) float As[128*36];
    __shared__ __align__(16) float Bs[64*36];
    __shared__ float cw4[4][128];
    __shared__ int   ci4[4][128];
    int tile = blockIdx.x;
    int b  = tile / 288;
    int pp0 = (tile - b*288) * 128;
    int tid = threadIdx.x;
    int lane = tid & 31;
    int warp = tid >> 5;
    int m0 = (warp & 3) * 32;
    int n0 = (warp >> 2) * 32;
    int g = lane >> 2, t = lane & 3;

    const float* xb = x + (size_t)b*Cn*HW;
    const uint32_t* Asu = (const uint32_t*)As;
    const uint32_t* Bsu = (const uint32_t*)Bs;

    float acc[2][4][4];
    #pragma unroll
    for (int mi=0;mi<2;mi++)
        #pragma unroll
        for (int ni=0;ni<4;ni++)
            #pragma unroll
            for (int j=0;j<4;j++) acc[mi][ni][j] = 0.f;

    for (int j = 0; j < 18; j++){
        int tap = j >> 1;
        int ci0 = (j & 1) * 32;
        __syncthreads();
        if ((j & 1) == 0 && tid < 128){
            int pix = tid;
            int pp = pp0 + pix;
            int gy = pp / Wn, gx = pp - (pp/Wn)*Wn;
            float dyv = g_om[((size_t)b*27 + 2*tap  )*HW + pp];
            float dxv = g_om[((size_t)b*27 + 2*tap+1)*HW + pp];
            float m   = g_om[((size_t)b*27 + 18+tap )*HW + pp];
            float py = (float)gy + (float)(tap/3 - 1) + dyv;
            float px = (float)gx + (float)(tap%3 - 1) + dxv;
            float fy = floorf(py), fx = floorf(px);
            int y0 = (int)fy, xq = (int)fx;
            float wy = py - fy, wx = px - fx;
            int y1 = y0+1, x1 = xq+1;
            int yc0 = min(max(y0,0),Hn-1), yc1 = min(max(y1,0),Hn-1);
            int xc0 = min(max(xq,0),Wn-1), xc1 = min(max(x1,0),Wn-1);
            float vy0 = (y0>=0 && y0<Hn)?1.f:0.f;
            float vy1 = (y1>=0 && y1<Hn)?1.f:0.f;
            float vx0 = (xq>=0 && xq<Wn)?1.f:0.f;
            float vx1 = (x1>=0 && x1<Wn)?1.f:0.f;
            cw4[0][pix] = (1.f-wy)*(1.f-wx)*vy0*vx0*m;  ci4[0][pix] = yc0*Wn+xc0;
            cw4[1][pix] = (1.f-wy)*wx     *vy0*vx1*m;   ci4[1][pix] = yc0*Wn+xc1;
            cw4[2][pix] = wy     *(1.f-wx)*vy1*vx0*m;   ci4[2][pix] = yc1*Wn+xc0;
            cw4[3][pix] = wy     *wx      *vy1*vx1*m;   ci4[3][pix] = yc1*Wn+xc1;
        }
        __syncthreads();
        // stage A: gather 128 pix x 32 ci
        #pragma unroll 4
        for (int it = 0; it < 16; it++){
            int tt = tid + it*256;
            int pix = tt & 127;
            int ci  = tt >> 7;
            const float* xc = xb + (size_t)(ci0 + ci)*HW;
            float v = cw4[0][pix]*__ldg(xc + ci4[0][pix])
                    + cw4[1][pix]*__ldg(xc + ci4[1][pix])
                    + cw4[2][pix]*__ldg(xc + ci4[2][pix])
                    + cw4[3][pix]*__ldg(xc + ci4[3][pix]);
            As[pix*36 + ci] = to_tf32(v);
        }
        // stage B
        #pragma unroll
        for (int it = 0; it < 2; it++){
            int id = tid + it*256;
            int f4 = id & 7;
            int co = id >> 3;
            float4 wv = *(const float4*)(g_wdcT2 + co*576 + tap*64 + ci0 + f4*4);
            *(float4*)&Bs[co*36 + f4*4] = wv;
        }
        __syncthreads();
        #pragma unroll
        for (int kk = 0; kk < 4; kk++){
            int k0 = kk*8;
            uint32_t afr[2][4], bfr[4][2];
            #pragma unroll
            for (int mi=0;mi<2;mi++){
                int r = m0 + mi*16;
                afr[mi][0] = Asu[(r+g  )*36 + k0 + t];
                afr[mi][1] = Asu[(r+g+8)*36 + k0 + t];
                afr[mi][2] = Asu[(r+g  )*36 + k0 + t + 4];
                afr[mi][3] = Asu[(r+g+8)*36 + k0 + t + 4];
            }
            #pragma unroll
            for (int ni=0;ni<4;ni++){
                int cN = n0 + ni*8 + g;
                bfr[ni][0] = Bsu[cN*36 + k0 + t];
                bfr[ni][1] = Bsu[cN*36 + k0 + t + 4];
            }
            #pragma unroll
            for (int mi=0;mi<2;mi++)
                #pragma unroll
                for (int ni=0;ni<4;ni++)
                    mma_tf32(acc[mi][ni], afr[mi], bfr[ni]);
        }
    }
    float* xdb = g_xd + (size_t)b*Cn*HW + pp0;
    #pragma unroll
    for (int mi=0;mi<2;mi++){
        int row = m0 + mi*16 + g;
        #pragma unroll
        for (int ni=0;ni<4;ni++){
            int col = n0 + ni*8 + 2*t;
            float b0 = __ldg(bias + col), b1 = __ldg(bias + col + 1);
            xdb[(size_t)col*HW     + row    ] = acc[mi][ni][0] + b0;
            xdb[(size_t)(col+1)*HW + row    ] = acc[mi][ni][1] + b1;
            xdb[(size_t)col*HW     + row + 8] = acc[mi][ni][2] + b0;
            xdb[(size_t)(col+1)*HW + row + 8] = acc[mi][ni][3] + b1;
        }
    }
}

// ---------------- channel mean over H,W ----------------
__global__ void __launch_bounds__(256) k_mean(){
    int bc = blockIdx.x;
    const float* p = g_xd + (size_t)bc*HW;
    float s = 0.f;
    for (int i=threadIdx.x; i<HW; i+=256) s += p[i];
    __shared__ float red[256];
    red[threadIdx.x] = s; __syncthreads();
    for (int o=128; o>0; o>>=1){
        if (threadIdx.x < o) red[threadIdx.x] += red[threadIdx.x+o];
        __syncthreads();
    }
    if (threadIdx.x==0) g_mean[bc] = red[0]*(1.f/HW);
}

// ---------------- channel attention MLP ----------------
__global__ void k_ca(const float* __restrict__ w1, const float* __restrict__ b1,
                     const float* __restrict__ w2, const float* __restrict__ b2){
    int b = blockIdx.x; int t = threadIdx.x;
    __shared__ float mn[64], h[8];
    mn[t] = g_mean[b*64+t];
    __syncthreads();
    if (t < 8){
        float s = __ldg(b1+t);
        for (int c=0;c<64;c++) s += __ldg(w1+t*64+c)*mn[c];
        h[t] = s > 0.f ? s : 0.f;
    }
    __syncthreads();
    float s = __ldg(b2+t);
    #pragma unroll
    for (int j=0;j<8;j++) s += __ldg(w2+t*8+j)*h[j];
    g_ca[b*64+t] = sigmoidf_(s);
}

// ---------------- spatial attention + xa = xd*(ca+sa) ----------------
__global__ void __launch_bounds__(256) k_saxa(const float* __restrict__ wsa,
                                              const float* __restrict__ bsa){
    __shared__ float sh[64*102];
    __shared__ float part[8][32];
    __shared__ float sav[32];
    int x0 = blockIdx.x*32, y = blockIdx.y, b = blockIdx.z;
    int tid = threadIdx.x;
    const float* xb = g_xd + (size_t)b*Cn*HW;
    for (int e=tid; e<64*102; e+=256){
        int ci = e/102; int r = e%102; int dy = r/34; int xx = r%34;
        int gy = y+dy-1, gx = x0+xx-1;
        sh[e] = (gy>=0 && gy<Hn && gx>=0 && gx<Wn) ? xb[ci*HW + gy*Wn + gx] : 0.f;
    }
    __syncthreads();
    int pix = tid&31, g = tid>>5;
    float acc = 0.f;
    for (int ci=g*8; ci<g*8+8; ci++){
        const float* s = sh + ci*102 + pix;
        const float* wp = wsa + ci*9;
        acc += s[0]*__ldg(wp+0) + s[1]*__ldg(wp+1) + s[2]*__ldg(wp+2)
             + s[34]*__ldg(wp+3) + s[35]*__ldg(wp+4) + s[36]*__ldg(wp+5)
             + s[68]*__ldg(wp+6) + s[69]*__ldg(wp+7) + s[70]*__ldg(wp+8);
    }
    part[g][pix] = acc;
    __syncthreads();
    if (g == 0){
        float t = __ldg(bsa);
        #pragma unroll
        for (int j=0;j<8;j++) t += part[j][pix];
        sav[pix] = sigmoidf_(t);
    }
    __syncthreads();
    float sa = sav[pix];
    for (int co=g; co<64; co+=8){
        float v = sh[co*102 + 34 + pix + 1];
        g_xa[((size_t)b*64+co)*HW + y*Wn + x0 + pix] = v * (g_ca[b*64+co] + sa);
    }
}

// ---------------- r1 via mma: 1x1 64->256, leaky, tf32-rounded output ----------------
// grid (1152, 4): blockIdx.y = cout chunk of 64
__global__ void __launch_bounds__(256) k_r1mma(const float* __restrict__ bias){
    __shared__ __align__(16) float As[128*36];
    __shared__ __align__(16) float Bs[64*36];
    int tile = blockIdx.x;
    int cob  = blockIdx.y * 64;
    int b  = tile / 288;
    int pp0 = (tile - b*288) * 128;
    int tid = threadIdx.x;
    int lane = tid & 31;
    int warp = tid >> 5;
    int m0 = (warp & 3) * 32;
    int n0 = (warp >> 2) * 32;
    int g = lane >> 2, t = lane & 3;

    const float* xab = g_xa + (size_t)b*Cn*HW;
    const uint32_t* Asu = (const uint32_t*)As;
    const uint32_t* Bsu = (const uint32_t*)Bs;

    float acc[2][4][4];
    #pragma unroll
    for (int mi=0;mi<2;mi++)
        #pragma unroll
        for (int ni=0;ni<4;ni++)
            #pragma unroll
            for (int j=0;j<4;j++) acc[mi][ni][j] = 0.f;

    #pragma unroll
    for (int j = 0; j < 2; j++){
        int ci0 = j*32;
        __syncthreads();
        // stage A from g_xa (no border logic)
        #pragma unroll
        for (int it = 0; it < 4; it++){
            int id = tid + it*256;
            int pix = id & 127;
            int j4  = id >> 7;
            const float* src = xab + (size_t)(ci0 + j4*4)*HW + pp0 + pix;
            float4 v;
            v.x = to_tf32(__ldg(src));
            v.y = to_tf32(__ldg(src + HW));
            v.z = to_tf32(__ldg(src + 2*HW));
            v.w = to_tf32(__ldg(src + 3*HW));
            *(float4*)&As[pix*36 + j4*4] = v;
        }
        // stage B
        #pragma unroll
        for (int it = 0; it < 2; it++){
            int id = tid + it*256;
            int f4 = id & 7;
            int co = id >> 3;
            float4 wv = *(const float4*)(g_wr1T2 + (size_t)(cob+co)*64 + ci0 + f4*4);
            *(float4*)&Bs[co*36 + f4*4] = wv;
        }
        __syncthreads();
        #pragma unroll
        for (int kk = 0; kk < 4; kk++){
            int k0 = kk*8;
            uint32_t afr[2][4], bfr[4][2];
            #pragma unroll
            for (int mi=0;mi<2;mi++){
                int r = m0 + mi*16;
                afr[mi][0] = Asu[(r+g  )*36 + k0 + t];
                afr[mi][1] = Asu[(r+g+8)*36 + k0 + t];
                afr[mi][2] = Asu[(r+g  )*36 + k0 + t + 4];
                afr[mi][3] = Asu[(r+g+8)*36 + k0 + t + 4];
            }
            #pragma unroll
            for (int ni=0;ni<4;ni++){
                int cN = n0 + ni*8 + g;
                bfr[ni][0] = Bsu[cN*36 + k0 + t];
                bfr[ni][1] = Bsu[cN*36 + k0 + t + 4];
            }
            #pragma unroll
            for (int mi=0;mi<2;mi++)
                #pragma unroll
                for (int ni=0;ni<4;ni++)
                    mma_tf32(acc[mi][ni], afr[mi], bfr[ni]);
        }
    }
    float* t1b = g_t1 + (size_t)b*CM*HW + pp0;
    #pragma unroll
    for (int mi=0;mi<2;mi++){
        int row = m0 + mi*16 + g;
        #pragma unroll
        for (int ni=0;ni<4;ni++){
            int col = cob + n0 + ni*8 + 2*t;
            float b0 = __ldg(bias + col), b1 = __ldg(bias + col + 1);
            t1b[(size_t)col*HW     + row    ] = to_tf32(leakyf_(acc[mi][ni][0] + b0));
            t1b[(size_t)(col+1)*HW + row    ] = to_tf32(leakyf_(acc[mi][ni][1] + b1));
            t1b[(size_t)col*HW     + row + 8] = to_tf32(leakyf_(acc[mi][ni][2] + b0));
            t1b[(size_t)(col+1)*HW + row + 8] = to_tf32(leakyf_(acc[mi][ni][3] + b1));
        }
    }
}

// ---------------- r2 via mma.sync tf32 (validated in R5) ----------------
__global__ void __launch_bounds__(256) k_r2mma(const float* __restrict__ bias){
    __shared__ __align__(16) float As[128*36];
    __shared__ __align__(16) float Bs[64*36];

    int tile = blockIdx.x;
    int b  = tile / 288;
    int p0 = (tile - b*288) * 128;
    int tid = threadIdx.x;
    int lane = tid & 31;
    int warp = tid >> 5;
    int m0 = (warp & 3) * 32;
    int n0 = (warp >> 2) * 32;
    int g = lane >> 2, t = lane & 3;

    const float* t1b = g_t1 + (size_t)b*CM*HW;
    const uint32_t* Asu = (const uint32_t*)As;
    const uint32_t* Bsu = (const uint32_t*)Bs;

    float acc[2][4][4];
    #pragma unroll
    for (int mi=0;mi<2;mi++)
        #pragma unroll
        for (int ni=0;ni<4;ni++)
            #pragma unroll
            for (int j=0;j<4;j++) acc[mi][ni][j] = 0.f;

    for (int j = 0; j < 72; j++){
        int tap = j >> 3;
        int cb  = (j & 7) * 32;
        int ty = tap/3 - 1, tx = tap - (tap/3)*3 - 1;
        int off = ty*Wn + tx;
        __syncthreads();
        #pragma unroll
        for (int it = 0; it < 4; it++){
            int id = tid + it*256;
            int p  = id & 127;
            int j4 = id >> 7;
            int q  = p0 + p;
            int qy = q / Wn;
            int qx = q - qy*Wn;
            int sy = qy + ty, sx = qx + tx;
            float4 v = make_float4(0.f, 0.f, 0.f, 0.f);
            if ((unsigned)sy < (unsigned)Hn && (unsigned)sx < (unsigned)Wn){
                const float* src = t1b + (size_t)(cb + j4*4)*HW + q + off;
                v.x = __ldg(src);
                v.y = __ldg(src + HW);
                v.z = __ldg(src + 2*HW);
                v.w = __ldg(src + 3*HW);
            }
            *(float4*)&As[p*36 + j4*4] = v;
        }
        const float* wsrc = g_wr2T + tap*256 + cb;
        #pragma unroll
        for (int it = 0; it < 2; it++){
            int id = tid + it*256;
            int f4 = id & 7;
            int co = id >> 3;
            float4 wv = *(const float4*)(wsrc + co*2304 + f4*4);
            *(float4*)&Bs[co*36 + f4*4] = wv;
        }
        __syncthreads();
        #pragma unroll
        for (int kk = 0; kk < 4; kk++){
            int k0 = kk*8;
            uint32_t afr[2][4], bfr[4][2];
            #pragma unroll
            for (int mi=0;mi<2;mi++){
                int r = m0 + mi*16;
                afr[mi][0] = Asu[(r+g  )*36 + k0 + t];
                afr[mi][1] = Asu[(r+g+8)*36 + k0 + t];
                afr[mi][2] = Asu[(r+g  )*36 + k0 + t + 4];
                afr[mi][3] = Asu[(r+g+8)*36 + k0 + t + 4];
            }
            #pragma unroll
            for (int ni=0;ni<4;ni++){
                int cN = n0 + ni*8 + g;
                bfr[ni][0] = Bsu[cN*36 + k0 + t];
                bfr[ni][1] = Bsu[cN*36 + k0 + t + 4];
            }
            #pragma unroll
            for (int mi=0;mi<2;mi++)
                #pragma unroll
                for (int ni=0;ni<4;ni++)
                    mma_tf32(acc[mi][ni], afr[mi], bfr[ni]);
        }
    }
    float* xrb = g_xr + (size_t)b*Cn*HW + p0;
    #pragma unroll
    for (int mi=0;mi<2;mi++){
        int row = m0 + mi*16 + g;
        #pragma unroll
        for (int ni=0;ni<4;ni++){
            int col = n0 + ni*8 + 2*t;
            float b0 = __ldg(bias + col), b1 = __ldg(bias + col + 1);
            xrb[(size_t)col*HW     + row    ] = acc[mi][ni][0] + b0;
            xrb[(size_t)(col+1)*HW + row    ] = acc[mi][ni][1] + b1;
            xrb[(size_t)col*HW     + row + 8] = acc[mi][ni][2] + b0;
            xrb[(size_t)(col+1)*HW + row + 8] = acc[mi][ni][3] + b1;
        }
    }
}

// ---------------- n1: 1x1, 64 -> 32 ----------------
__global__ void __launch_bounds__(256) k_n1(const float* __restrict__ bias){
    __shared__ float sh[64*32];
    int p0 = blockIdx.x*32; int b = p0/HW; int sp = p0%HW;
    int tid = threadIdx.x;
    for (int e=tid; e<64*32; e+=256){
        int ci=e>>5, pix=e&31;
        sh[e] = g_xa[((size_t)b*64+ci)*HW + sp + pix];
    }
    __syncthreads();
    int pix = tid&31, g = tid>>5;
    int co0 = g*4;
    float acc[4];
    #pragma unroll
    for (int j=0;j<4;j++) acc[j] = __ldg(bias+co0+j);
    #pragma unroll 4
    for (int ci=0; ci<64; ci++){
        float v = sh[ci*32+pix];
        float4 wa = *(const float4*)&g_wn1T[ci*32+co0];
        acc[0]+=v*wa.x; acc[1]+=v*wa.y; acc[2]+=v*wa.z; acc[3]+=v*wa.w;
    }
    #pragma unroll
    for (int j=0;j<4;j++)
        g_n1[((size_t)b*CH+co0+j)*HW + sp + pix] = acc[j];
}

// ---------------- n2: depthwise 3x3 pad1 on 32 channels ----------------
__global__ void __launch_bounds__(256) k_n2(const float* __restrict__ w,
                                            const float* __restrict__ bias){
    int idx = blockIdx.x*256 + threadIdx.x;
    if (idx >= Bn*CH*HW) return;
    int pp = idx % HW; int bc = idx / HW; int c = bc % CH;
    int gy = pp/Wn, gx = pp%Wn;
    const float* in = g_n1 + (size_t)bc*HW;
    float acc = __ldg(bias+c);
    #pragma unroll
    for (int ky=0;ky<3;ky++){
        int yy = gy+ky-1;
        if (yy<0 || yy>=Hn) continue;
        #pragma unroll
        for (int kx=0;kx<3;kx++){
            int xx = gx+kx-1;
            if (xx<0 || xx>=Wn) continue;
            acc += in[yy*Wn+xx]*__ldg(w + c*9 + ky*3 + kx);
        }
    }
    g_n2[idx] = acc;
}

// ---------------- final: out = x + xr + (1x1 32->64)(n2) ----------------
__global__ void __launch_bounds__(256) k_final(const float* __restrict__ x,
                                               const float* __restrict__ bias,
                                               float* __restrict__ out){
    __shared__ float sh[32*32];
    int p0 = blockIdx.x*32; int b = p0/HW; int sp = p0%HW;
    int tid = threadIdx.x;
    for (int e=tid; e<32*32; e+=256){
        int ci=e>>5, pix=e&31;
        sh[e] = g_n2[((size_t)b*CH+ci)*HW + sp + pix];
    }
    __syncthreads();
    int pix = tid&31, g = tid>>5;
    int co0 = g*8;
    float acc[8];
    #pragma unroll
    for (int j=0;j<8;j++) acc[j] = __ldg(bias+co0+j);
    #pragma unroll 4
    for (int ci=0; ci<32; ci++){
        float v = sh[ci*32+pix];
        float4 wa = *(const float4*)&g_wn3T[ci*64+co0];
        float4 wb = *(const float4*)&g_wn3T[ci*64+co0+4];
        acc[0]+=v*wa.x; acc[1]+=v*wa.y; acc[2]+=v*wa.z; acc[3]+=v*wa.w;
        acc[4]+=v*wb.x; acc[5]+=v*wb.y; acc[6]+=v*wb.z; acc[7]+=v*wb.w;
    }
    #pragma unroll
    for (int j=0;j<8;j++){
        size_t o = ((size_t)b*64+co0+j)*HW + sp + pix;
        out[o] = x[o] + g_xr[o] + acc[j];
    }
}

// ---------------- launch ----------------
extern "C" void kernel_launch(void* const* d_in, const int* in_sizes, int n_in,
                              void* d_out, int out_size){
    const float* x     = (const float*)d_in[0];
    const float* w_off = (const float*)d_in[1];
    const float* b_off = (const float*)d_in[2];
    const float* w_dc  = (const float*)d_in[3];
    const float* b_dc  = (const float*)d_in[4];
    const float* w_ca1 = (const float*)d_in[5];
    const float* b_ca1 = (const float*)d_in[6];
    const float* w_ca2 = (const float*)d_in[7];
    const float* b_ca2 = (const float*)d_in[8];
    const float* w_sa  = (const float*)d_in[9];
    const float* b_sa  = (const float*)d_in[10];
    const float* w_r1  = (const float*)d_in[11];
    const float* b_r1  = (const float*)d_in[12];
    const float* w_r2  = (const float*)d_in[13];
    const float* b_r2  = (const float*)d_in[14];
    const float* w_n1  = (const float*)d_in[15];
    const float* b_n1  = (const float*)d_in[16];
    const float* w_n2  = (const float*)d_in[17];
    const float* b_n2  = (const float*)d_in[18];
    const float* w_n3  = (const float*)d_in[19];
    const float* b_n3  = (const float*)d_in[20];
    float* out = (float*)d_out;

    k_prep<<<256, 256>>>(w_off, w_dc, w_r2, w_r1, w_n1, w_n3);
    k_offmma<<<1152, 256>>>(x, b_off);
    k_deform_mma<<<1152, 256>>>(x, b_dc);
    k_mean<<<Bn*Cn, 256>>>();
    k_ca<<<Bn, 64>>>(w_ca1, b_ca1, w_ca2, b_ca2);
    k_saxa<<<dim3(Wn/32, Hn, Bn), 256>>>(w_sa, b_sa);
    k_r1mma<<<dim3(1152, 4), 256>>>(b_r1);
    k_r2mma<<<1152, 256>>>(b_r2);
    k_n1<<<(Bn*HW)/32, 256>>>(b_n1);
    k_n2<<<(Bn*CH*HW + 255)/256, 256>>>(w_n2, b_n2);
    k_final<<<(Bn*HW)/32, 256>>>(x, b_n3, out);
}

// round 12
// speedup vs baseline: 3.7144x; 1.1046x over previous
#include <cuda_runtime.h>
#include <math.h>
#include <stdint.h>

#define Bn 4
#define Cn 64
#define Hn 192
#define Wn 192
#define HW (Hn*Wn)      // 36864
#define CM 256          // C*EXP
#define CH 32           // C/2

// ---------------- scratch (static device globals; no allocation) ----------------
__device__ float g_om  [Bn*27*HW];
__device__ float g_xd  [Bn*Cn*HW];
__device__ float g_mean[Bn*Cn];
__device__ float g_ca  [Bn*Cn];
__device__ float g_xa  [Bn*Cn*HW];
__device__ float g_t1  [Bn*CM*HW];
__device__ float g_xr  [Bn*Cn*HW];
__device__ float g_n1  [Bn*CH*HW];
__device__ float g_n2  [Bn*CH*HW];
// transposed weights (tf32-rounded where used by MMA)
__device__ __align__(16) float g_woffT[32*576];    // [co(pad32)][tap*64+ci]
__device__ __align__(16) float g_wdcT2[64*576];    // [co][tap*64+ci]
__device__ __align__(16) float g_wr1T2[256*64];    // [co][ci]
__device__ __align__(16) float g_wr2T[64*2304];    // [co][tap*256+cin]
__device__ __align__(16) float g_wn1T[64*32];
__device__ __align__(16) float g_wn3T[32*64];

__device__ __forceinline__ float sigmoidf_(float v){ return 1.f/(1.f+expf(-v)); }
__device__ __forceinline__ float leakyf_(float v){ return v >= 0.f ? v : 0.1f*v; }
__device__ __forceinline__ float to_tf32(float v){
    uint32_t r; asm("cvt.rna.tf32.f32 %0, %1;" : "=r"(r) : "f"(v));
    return __uint_as_float(r);
}
__device__ __forceinline__ void mma_tf32(float* c, const uint32_t* a, const uint32_t* b){
    asm volatile("mma.sync.aligned.m16n8k8.row.col.f32.tf32.tf32.f32 "
        "{%0,%1,%2,%3}, {%4,%5,%6,%7}, {%8,%9}, {%0,%1,%2,%3};"
        : "+f"(c[0]), "+f"(c[1]), "+f"(c[2]), "+f"(c[3])
        : "r"(a[0]), "r"(a[1]), "r"(a[2]), "r"(a[3]), "r"(b[0]), "r"(b[1]));
}

// ---------------- weight transposes ----------------
__global__ void k_prep(const float* __restrict__ woff, const float* __restrict__ wdc,
                       const float* __restrict__ wr2,  const float* __restrict__ wr1,
                       const float* __restrict__ wn1,  const float* __restrict__ wn3){
    int stride = gridDim.x*blockDim.x;
    int i0 = blockIdx.x*blockDim.x + threadIdx.x;
    for (int t=i0; t<32*576; t+=stride){
        int co = t/576; int r = t - co*576; int tap = r>>6; int ci = r&63;
        g_woffT[t] = (co < 27) ? to_tf32(woff[co*576 + ci*9 + tap]) : 0.f;
    }
    for (int t=i0; t<64*576; t+=stride){
        int co = t/576; int r = t - co*576; int tap = r>>6; int ci = r&63;
        g_wdcT2[t] = to_tf32(wdc[co*576 + ci*9 + tap]);
    }
    for (int t=i0; t<64*2304; t+=stride){
        int co = t/2304; int r = t - co*2304; int tap = r>>8; int cin = r&255;
        g_wr2T[t] = to_tf32(wr2[co*2304 + cin*9 + tap]);
    }
    for (int t=i0; t<256*64; t+=stride){ g_wr1T2[t] = to_tf32(wr1[t]); }
    for (int t=i0; t<64*32;  t+=stride){ int ci=t>>5, co=t&31; g_wn1T[t] = wn1[co*64 + ci]; }
    for (int t=i0; t<32*64;  t+=stride){ int ci=t>>6, co=t&63; g_wn3T[t] = wn3[co*32 + ci]; }
}

// ---------------- offset conv via halo-mma: 27(pad32) <- 64x3x3 ----------------
// 2D tile: 8 rows x 16 cols. Halo 10x18 staged once per ci chunk, serves 9 taps.
__global__ void __launch_bounds__(256) k_offmma(const float* __restrict__ x,
                                                const float* __restrict__ bias){
    __shared__ __align__(16) float Ah[180*36];
    __shared__ __align__(16) float Bs[2][32*36];
    int X0 = blockIdx.x*16, Y0 = blockIdx.y*8, b = blockIdx.z;
    int tid = threadIdx.x;
    int lane = tid & 31;
    int warp = tid >> 5;
    int m0 = warp * 16;                    // 8 warps x 16 rows = 128
    int g = lane >> 2, t = lane & 3;
    int hb0 = (m0 >> 4)*18 + g;            // = warp*18 + g

    const float* xb = x + (size_t)b*Cn*HW;
    const uint32_t* Asu = (const uint32_t*)Ah;

    float acc[4][4];
    #pragma unroll
    for (int ni=0;ni<4;ni++)
        #pragma unroll
        for (int j=0;j<4;j++) acc[ni][j] = 0.f;

    for (int cb = 0; cb < 2; cb++){
        int ci0 = cb*32;
        __syncthreads();
        // stage halo A: 180 pixels x 32 ci
        for (int id = tid; id < 5760; id += 256){
            int ci = id/180, pk = id - ci*180;
            int hy = pk/18, hx = pk - hy*18;
            int gy = Y0 + hy - 1, gx = X0 + hx - 1;
            float v = 0.f;
            if ((unsigned)gy < (unsigned)Hn && (unsigned)gx < (unsigned)Wn)
                v = to_tf32(__ldg(xb + (size_t)(ci0+ci)*HW + gy*Wn + gx));
            Ah[pk*36 + ci] = v;
        }
        // stage B tap0 -> buf0
        {
            int co = tid >> 3, f4 = tid & 7;
            *(float4*)&Bs[0][co*36 + f4*4] =
                *(const float4*)(g_woffT + co*576 + ci0 + f4*4);
        }
        for (int tap = 0; tap < 9; tap++){
            __syncthreads();
            if (tap < 8){
                int co = tid >> 3, f4 = tid & 7;
                *(float4*)&Bs[(tap+1)&1][co*36 + f4*4] =
                    *(const float4*)(g_woffT + co*576 + (tap+1)*64 + ci0 + f4*4);
            }
            const uint32_t* Bsu = (const uint32_t*)Bs[tap&1];
            int toff = (tap/3)*18 + tap - (tap/3)*3;
            int hh = hb0 + toff;
            #pragma unroll
            for (int kk = 0; kk < 4; kk++){
                int k0 = kk*8;
                uint32_t afr[4], bfr[4][2];
                afr[0] = Asu[hh*36 + k0 + t];
                afr[1] = Asu[(hh+8)*36 + k0 + t];
                afr[2] = Asu[hh*36 + k0 + t + 4];
                afr[3] = Asu[(hh+8)*36 + k0 + t + 4];
                #pragma unroll
                for (int ni=0;ni<4;ni++){
                    int cN = ni*8 + g;
                    bfr[ni][0] = Bsu[cN*36 + k0 + t];
                    bfr[ni][1] = Bsu[cN*36 + k0 + t + 4];
                }
                #pragma unroll
                for (int ni=0;ni<4;ni++)
                    mma_tf32(acc[ni], afr, bfr[ni]);
            }
        }
    }
    // epilogue
    int yy = Y0 + warp;                    // tile row for this warp
    float* omb = g_om + (size_t)b*27*HW;
    int q0 = yy*Wn + X0 + g;
    #pragma unroll
    for (int ni=0;ni<4;ni++){
        int cN = ni*8 + 2*t;
        #pragma unroll
        for (int u=0;u<2;u++){
            int c = cN + u;
            if (c < 27){
                float bb = __ldg(bias + c);
                float v0 = leakyf_(acc[ni][u]   + bb);
                float v1 = leakyf_(acc[ni][2+u] + bb);
                if (c >= 18){ v0 = sigmoidf_(v0); v1 = sigmoidf_(v1); }
                omb[(size_t)c*HW + q0    ] = v0;
                omb[(size_t)c*HW + q0 + 8] = v1;
            }
        }
    }
}

// ---------------- deformable conv via mma (linear tiles) ----------------
__global__ void __launch_bounds__(256) k_deform_mma(const float* __restrict__ x,
                                                    const float* __restrict__ bias){
    __shared__ __align__(16) float As[128*36];
    __shared__ __align__(16) float Bs[64*36];
    __shared__ float cw4[4][128];
    __shared__ int   ci4[4][128];
    int tile = blockIdx.x;
    int b  = tile / 288;
    int pp0 = (tile - b*288) * 128;
    int tid = threadIdx.x;
    int lane = tid & 31;
    int warp = tid >> 5;
    int m0 = (warp & 3) * 32;
    int n0 = (warp >> 2) * 32;
    int g = lane >> 2, t = lane & 3;

    const float* xb = x + (size_t)b*Cn*HW;
    const uint32_t* Asu = (const uint32_t*)As;
    const uint32_t* Bsu = (const uint32_t*)Bs;

    float acc[2][4][4];
    #pragma unroll
    for (int mi=0;mi<2;mi++)
        #pragma unroll
        for (int ni=0;ni<4;ni++)
            #pragma unroll
            for (int j=0;j<4;j++) acc[mi][ni][j] = 0.f;

    for (int j = 0; j < 18; j++){
        int tap = j >> 1;
        int ci0 = (j & 1) * 32;
        __syncthreads();
        if ((j & 1) == 0 && tid < 128){
            int pix = tid;
            int pp = pp0 + pix;
            int gy = pp / Wn, gx = pp - (pp/Wn)*Wn;
            float dyv = g_om[((size_t)b*27 + 2*tap  )*HW + pp];
            float dxv = g_om[((size_t)b*27 + 2*tap+1)*HW + pp];
            float m   = g_om[((size_t)b*27 + 18+tap )*HW + pp];
            float py = (float)gy + (float)(tap/3 - 1) + dyv;
            float px = (float)gx + (float)(tap%3 - 1) + dxv;
            float fy = floorf(py), fx = floorf(px);
            int y0 = (int)fy, xq = (int)fx;
            float wy = py - fy, wx = px - fx;
            int y1 = y0+1, x1 = xq+1;
            int yc0 = min(max(y0,0),Hn-1), yc1 = min(max(y1,0),Hn-1);
            int xc0 = min(max(xq,0),Wn-1), xc1 = min(max(x1,0),Wn-1);
            float vy0 = (y0>=0 && y0<Hn)?1.f:0.f;
            float vy1 = (y1>=0 && y1<Hn)?1.f:0.f;
            float vx0 = (xq>=0 && xq<Wn)?1.f:0.f;
            float vx1 = (x1>=0 && x1<Wn)?1.f:0.f;
            cw4[0][pix] = (1.f-wy)*(1.f-wx)*vy0*vx0*m;  ci4[0][pix] = yc0*Wn+xc0;
            cw4[1][pix] = (1.f-wy)*wx     *vy0*vx1*m;   ci4[1][pix] = yc0*Wn+xc1;
            cw4[2][pix] = wy     *(1.f-wx)*vy1*vx0*m;   ci4[2][pix] = yc1*Wn+xc0;
            cw4[3][pix] = wy     *wx      *vy1*vx1*m;   ci4[3][pix] = yc1*Wn+xc1;
        }
        __syncthreads();
        #pragma unroll 4
        for (int it = 0; it < 16; it++){
            int tt = tid + it*256;
            int pix = tt & 127;
            int ci  = tt >> 7;
            const float* xc = xb + (size_t)(ci0 + ci)*HW;
            float v = cw4[0][pix]*__ldg(xc + ci4[0][pix])
                    + cw4[1][pix]*__ldg(xc + ci4[1][pix])
                    + cw4[2][pix]*__ldg(xc + ci4[2][pix])
                    + cw4[3][pix]*__ldg(xc + ci4[3][pix]);
            As[pix*36 + ci] = to_tf32(v);
        }
        #pragma unroll
        for (int it = 0; it < 2; it++){
            int id = tid + it*256;
            int f4 = id & 7;
            int co = id >> 3;
            float4 wv = *(const float4*)(g_wdcT2 + co*576 + tap*64 + ci0 + f4*4);
            *(float4*)&Bs[co*36 + f4*4] = wv;
        }
        __syncthreads();
        #pragma unroll
        for (int kk = 0; kk < 4; kk++){
            int k0 = kk*8;
            uint32_t afr[2][4], bfr[4][2];
            #pragma unroll
            for (int mi=0;mi<2;mi++){
                int r = m0 + mi*16;
                afr[mi][0] = Asu[(r+g  )*36 + k0 + t];
                afr[mi][1] = Asu[(r+g+8)*36 + k0 + t];
                afr[mi][2] = Asu[(r+g  )*36 + k0 + t + 4];
                afr[mi][3] = Asu[(r+g+8)*36 + k0 + t + 4];
            }
            #pragma unroll
            for (int ni=0;ni<4;ni++){
                int cN = n0 + ni*8 + g;
                bfr[ni][0] = Bsu[cN*36 + k0 + t];
                bfr[ni][1] = Bsu[cN*36 + k0 + t + 4];
            }
            #pragma unroll
            for (int mi=0;mi<2;mi++)
                #pragma unroll
                for (int ni=0;ni<4;ni++)
                    mma_tf32(acc[mi][ni], afr[mi], bfr[ni]);
        }
    }
    float* xdb = g_xd + (size_t)b*Cn*HW + pp0;
    #pragma unroll
    for (int mi=0;mi<2;mi++){
        int row = m0 + mi*16 + g;
        #pragma unroll
        for (int ni=0;ni<4;ni++){
            int col = n0 + ni*8 + 2*t;
            float b0 = __ldg(bias + col), b1 = __ldg(bias + col + 1);
            xdb[(size_t)col*HW     + row    ] = acc[mi][ni][0] + b0;
            xdb[(size_t)(col+1)*HW + row    ] = acc[mi][ni][1] + b1;
            xdb[(size_t)col*HW     + row + 8] = acc[mi][ni][2] + b0;
            xdb[(size_t)(col+1)*HW + row + 8] = acc[mi][ni][3] + b1;
        }
    }
}

// ---------------- channel mean over H,W ----------------
__global__ void __launch_bounds__(256) k_mean(){
    int bc = blockIdx.x;
    const float* p = g_xd + (size_t)bc*HW;
    float s = 0.f;
    for (int i=threadIdx.x; i<HW; i+=256) s += p[i];
    __shared__ float red[256];
    red[threadIdx.x] = s; __syncthreads();
    for (int o=128; o>0; o>>=1){
        if (threadIdx.x < o) red[threadIdx.x] += red[threadIdx.x+o];
        __syncthreads();
    }
    if (threadIdx.x==0) g_mean[bc] = red[0]*(1.f/HW);
}

// ---------------- channel attention MLP ----------------
__global__ void k_ca(const float* __restrict__ w1, const float* __restrict__ b1,
                     const float* __restrict__ w2, const float* __restrict__ b2){
    int b = blockIdx.x; int t = threadIdx.x;
    __shared__ float mn[64], h[8];
    mn[t] = g_mean[b*64+t];
    __syncthreads();
    if (t < 8){
        float s = __ldg(b1+t);
        for (int c=0;c<64;c++) s += __ldg(w1+t*64+c)*mn[c];
        h[t] = s > 0.f ? s : 0.f;
    }
    __syncthreads();
    float s = __ldg(b2+t);
    #pragma unroll
    for (int j=0;j<8;j++) s += __ldg(w2+t*8+j)*h[j];
    g_ca[b*64+t] = sigmoidf_(s);
}

// ---------------- spatial attention + xa = xd*(ca+sa) ----------------
__global__ void __launch_bounds__(256) k_saxa(const float* __restrict__ wsa,
                                              const float* __restrict__ bsa){
    __shared__ float sh[64*102];
    __shared__ float part[8][32];
    __shared__ float sav[32];
    int x0 = blockIdx.x*32, y = blockIdx.y, b = blockIdx.z;
    int tid = threadIdx.x;
    const float* xb = g_xd + (size_t)b*Cn*HW;
    for (int e=tid; e<64*102; e+=256){
        int ci = e/102; int r = e%102; int dy = r/34; int xx = r%34;
        int gy = y+dy-1, gx = x0+xx-1;
        sh[e] = (gy>=0 && gy<Hn && gx>=0 && gx<Wn) ? xb[ci*HW + gy*Wn + gx] : 0.f;
    }
    __syncthreads();
    int pix = tid&31, g = tid>>5;
    float acc = 0.f;
    for (int ci=g*8; ci<g*8+8; ci++){
        const float* s = sh + ci*102 + pix;
        const float* wp = wsa + ci*9;
        acc += s[0]*__ldg(wp+0) + s[1]*__ldg(wp+1) + s[2]*__ldg(wp+2)
             + s[34]*__ldg(wp+3) + s[35]*__ldg(wp+4) + s[36]*__ldg(wp+5)
             + s[68]*__ldg(wp+6) + s[69]*__ldg(wp+7) + s[70]*__ldg(wp+8);
    }
    part[g][pix] = acc;
    __syncthreads();
    if (g == 0){
        float t = __ldg(bsa);
        #pragma unroll
        for (int j=0;j<8;j++) t += part[j][pix];
        sav[pix] = sigmoidf_(t);
    }
    __syncthreads();
    float sa = sav[pix];
    for (int co=g; co<64; co+=8){
        float v = sh[co*102 + 34 + pix + 1];
        g_xa[((size_t)b*64+co)*HW + y*Wn + x0 + pix] = v * (g_ca[b*64+co] + sa);
    }
}

// ---------------- r1 via mma: 1x1 64->256, A staged ONCE, loop 4 cout chunks ----------------
__global__ void __launch_bounds__(256) k_r1mma(const float* __restrict__ bias){
    __shared__ __align__(16) float As[128*76];   // ci j-block at col j*40
    __shared__ __align__(16) float Bs[64*36];
    int tile = blockIdx.x;
    int b  = tile / 288;
    int pp0 = (tile - b*288) * 128;
    int tid = threadIdx.x;
    int lane = tid & 31;
    int warp = tid >> 5;
    int m0 = (warp & 3) * 32;
    int n0 = (warp >> 2) * 32;
    int g = lane >> 2, t = lane & 3;

    const float* xab = g_xa + (size_t)b*Cn*HW;
    const uint32_t* Asu = (const uint32_t*)As;
    const uint32_t* Bsu = (const uint32_t*)Bs;

    // stage full A (64 ci) once
    #pragma unroll
    for (int it = 0; it < 8; it++){
        int id = tid + it*256;
        int pix = id & 127;
        int f   = id >> 7;                 // 0..15
        int cia = (f>>3)*32 + (f&7)*4;
        int col = (f>>3)*40 + (f&7)*4;
        const float* src = xab + (size_t)cia*HW + pp0 + pix;
        float4 v;
        v.x = to_tf32(__ldg(src));
        v.y = to_tf32(__ldg(src + HW));
        v.z = to_tf32(__ldg(src + 2*HW));
        v.w = to_tf32(__ldg(src + 3*HW));
        *(float4*)&As[pix*76 + col] = v;
    }

    for (int cob = 0; cob < 4; cob++){
        float acc[2][4][4];
        #pragma unroll
        for (int mi=0;mi<2;mi++)
            #pragma unroll
            for (int ni=0;ni<4;ni++)
                #pragma unroll
                for (int j=0;j<4;j++) acc[mi][ni][j] = 0.f;
        #pragma unroll
        for (int j = 0; j < 2; j++){
            __syncthreads();
            #pragma unroll
            for (int it = 0; it < 2; it++){
                int id = tid + it*256;
                int f4 = id & 7;
                int co = id >> 3;
                *(float4*)&Bs[co*36 + f4*4] =
                    *(const float4*)(g_wr1T2 + (size_t)(cob*64+co)*64 + j*32 + f4*4);
            }
            __syncthreads();
            #pragma unroll
            for (int kk = 0; kk < 4; kk++){
                int kA = j*40 + kk*8;
                int kB = kk*8;
                uint32_t afr[2][4], bfr[4][2];
                #pragma unroll
                for (int mi=0;mi<2;mi++){
                    int r = m0 + mi*16;
                    afr[mi][0] = Asu[(r+g  )*76 + kA + t];
                    afr[mi][1] = Asu[(r+g+8)*76 + kA + t];
                    afr[mi][2] = Asu[(r+g  )*76 + kA + t + 4];
                    afr[mi][3] = Asu[(r+g+8)*76 + kA + t + 4];
                }
                #pragma unroll
                for (int ni=0;ni<4;ni++){
                    int cN = n0 + ni*8 + g;
                    bfr[ni][0] = Bsu[cN*36 + kB + t];
                    bfr[ni][1] = Bsu[cN*36 + kB + t + 4];
                }
                #pragma unroll
                for (int mi=0;mi<2;mi++)
                    #pragma unroll
                    for (int ni=0;ni<4;ni++)
                        mma_tf32(acc[mi][ni], afr[mi], bfr[ni]);
            }
        }
        float* t1b = g_t1 + (size_t)b*CM*HW + pp0;
        #pragma unroll
        for (int mi=0;mi<2;mi++){
            int row = m0 + mi*16 + g;
            #pragma unroll
            for (int ni=0;ni<4;ni++){
                int col = cob*64 + n0 + ni*8 + 2*t;
                float b0 = __ldg(bias + col), b1 = __ldg(bias + col + 1);
                t1b[(size_t)col*HW     + row    ] = to_tf32(leakyf_(acc[mi][ni][0] + b0));
                t1b[(size_t)(col+1)*HW + row    ] = to_tf32(leakyf_(acc[mi][ni][1] + b1));
                t1b[(size_t)col*HW     + row + 8] = to_tf32(leakyf_(acc[mi][ni][2] + b0));
                t1b[(size_t)(col+1)*HW + row + 8] = to_tf32(leakyf_(acc[mi][ni][3] + b1));
            }
        }
    }
}

// ---------------- r2 via halo-mma: 3x3 256->64, 2D tile 8x16, halo staged once/chunk ----------------
__global__ void __launch_bounds__(256) k_r2mma(const float* __restrict__ bias){
    __shared__ __align__(16) float Ah[180*36];
    __shared__ __align__(16) float Bs[2][64*36];
    int X0 = blockIdx.x*16, Y0 = blockIdx.y*8, b = blockIdx.z;
    int tid = threadIdx.x;
    int lane = tid & 31;
    int warp = tid >> 5;
    int m0 = (warp & 3) * 32;
    int n0 = (warp >> 2) * 32;
    int g = lane >> 2, t = lane & 3;
    int hb0 = (m0 >> 4)*18 + g;

    const float* t1b = g_t1 + (size_t)b*CM*HW;
    const uint32_t* Asu = (const uint32_t*)Ah;

    float acc[2][4][4];
    #pragma unroll
    for (int mi=0;mi<2;mi++)
        #pragma unroll
        for (int ni=0;ni<4;ni++)
            #pragma unroll
            for (int j=0;j<4;j++) acc[mi][ni][j] = 0.f;

    for (int cb = 0; cb < 8; cb++){
        int ci0 = cb*32;
        __syncthreads();
        // stage halo A: 180 pixels x 32 ci
        for (int id = tid; id < 5760; id += 256){
            int ci = id/180, pk = id - ci*180;
            int hy = pk/18, hx = pk - hy*18;
            int gy = Y0 + hy - 1, gx = X0 + hx - 1;
            float v = 0.f;
            if ((unsigned)gy < (unsigned)Hn && (unsigned)gx < (unsigned)Wn)
                v = __ldg(t1b + (size_t)(ci0+ci)*HW + gy*Wn + gx);
            Ah[pk*36 + ci] = v;
        }
        // stage B tap0 -> buf0
        #pragma unroll
        for (int it = 0; it < 2; it++){
            int id = tid + it*256;
            int f4 = id & 7;
            int co = id >> 3;
            *(float4*)&Bs[0][co*36 + f4*4] =
                *(const float4*)(g_wr2T + co*2304 + ci0 + f4*4);
        }
        for (int tap = 0; tap < 9; tap++){
            __syncthreads();
            if (tap < 8){
                #pragma unroll
                for (int it = 0; it < 2; it++){
                    int id = tid + it*256;
                    int f4 = id & 7;
                    int co = id >> 3;
                    *(float4*)&Bs[(tap+1)&1][co*36 + f4*4] =
                        *(const float4*)(g_wr2T + co*2304 + (tap+1)*256 + ci0 + f4*4);
                }
            }
            const uint32_t* Bsu = (const uint32_t*)Bs[tap&1];
            int toff = (tap/3)*18 + tap - (tap/3)*3;
            #pragma unroll
            for (int kk = 0; kk < 4; kk++){
                int k0 = kk*8;
                uint32_t afr[2][4], bfr[4][2];
                #pragma unroll
                for (int mi=0;mi<2;mi++){
                    int hh = hb0 + mi*18 + toff;
                    afr[mi][0] = Asu[hh*36 + k0 + t];
                    afr[mi][1] = Asu[(hh+8)*36 + k0 + t];
                    afr[mi][2] = Asu[hh*36 + k0 + t + 4];
                    afr[mi][3] = Asu[(hh+8)*36 + k0 + t + 4];
                }
                #pragma unroll
                for (int ni=0;ni<4;ni++){
                    int cN = n0 + ni*8 + g;
                    bfr[ni][0] = Bsu[cN*36 + k0 + t];
                    bfr[ni][1] = Bsu[cN*36 + k0 + t + 4];
                }
                #pragma unroll
                for (int mi=0;mi<2;mi++)
                    #pragma unroll
                    for (int ni=0;ni<4;ni++)
                        mma_tf32(acc[mi][ni], afr[mi], bfr[ni]);
            }
        }
    }
    // epilogue: 2D scatter
    float* xrb = g_xr + (size_t)b*Cn*HW;
    int ybase = Y0 + (m0 >> 4);
    #pragma unroll
    for (int mi=0;mi<2;mi++){
        int q0 = (ybase + mi)*Wn + X0 + g;
        #pragma unroll
        for (int ni=0;ni<4;ni++){
            int col = n0 + ni*8 + 2*t;
            float b0 = __ldg(bias + col), b1 = __ldg(bias + col + 1);
            xrb[(size_t)col*HW     + q0    ] = acc[mi][ni][0] + b0;
            xrb[(size_t)(col+1)*HW + q0    ] = acc[mi][ni][1] + b1;
            xrb[(size_t)col*HW     + q0 + 8] = acc[mi][ni][2] + b0;
            xrb[(size_t)(col+1)*HW + q0 + 8] = acc[mi][ni][3] + b1;
        }
    }
}

// ---------------- n1: 1x1, 64 -> 32 ----------------
__global__ void __launch_bounds__(256) k_n1(const float* __restrict__ bias){
    __shared__ float sh[64*32];
    int p0 = blockIdx.x*32; int b = p0/HW; int sp = p0%HW;
    int tid = threadIdx.x;
    for (int e=tid; e<64*32; e+=256){
        int ci=e>>5, pix=e&31;
        sh[e] = g_xa[((size_t)b*64+ci)*HW + sp + pix];
    }
    __syncthreads();
    int pix = tid&31, g = tid>>5;
    int co0 = g*4;
    float acc[4];
    #pragma unroll
    for (int j=0;j<4;j++) acc[j] = __ldg(bias+co0+j);
    #pragma unroll 4
    for (int ci=0; ci<64; ci++){
        float v = sh[ci*32+pix];
        float4 wa = *(const float4*)&g_wn1T[ci*32+co0];
        acc[0]+=v*wa.x; acc[1]+=v*wa.y; acc[2]+=v*wa.z; acc[3]+=v*wa.w;
    }
    #pragma unroll
    for (int j=0;j<4;j++)
        g_n1[((size_t)b*CH+co0+j)*HW + sp + pix] = acc[j];
}

// ---------------- n2: depthwise 3x3 pad1 on 32 channels ----------------
__global__ void __launch_bounds__(256) k_n2(const float* __restrict__ w,
                                            const float* __restrict__ bias){
    int idx = blockIdx.x*256 + threadIdx.x;
    if (idx >= Bn*CH*HW) return;
    int pp = idx % HW; int bc = idx / HW; int c = bc % CH;
    int gy = pp/Wn, gx = pp%Wn;
    const float* in = g_n1 + (size_t)bc*HW;
    float acc = __ldg(bias+c);
    #pragma unroll
    for (int ky=0;ky<3;ky++){
        int yy = gy+ky-1;
        if (yy<0 || yy>=Hn) continue;
        #pragma unroll
        for (int kx=0;kx<3;kx++){
            int xx = gx+kx-1;
            if (xx<0 || xx>=Wn) continue;
            acc += in[yy*Wn+xx]*__ldg(w + c*9 + ky*3 + kx);
        }
    }
    g_n2[idx] = acc;
}

// ---------------- final: out = x + xr + (1x1 32->64)(n2) ----------------
__global__ void __launch_bounds__(256) k_final(const float* __restrict__ x,
                                               const float* __restrict__ bias,
                                               float* __restrict__ out){
    __shared__ float sh[32*32];
    int p0 = blockIdx.x*32; int b = p0/HW; int sp = p0%HW;
    int tid = threadIdx.x;
    for (int e=tid; e<32*32; e+=256){
        int ci=e>>5, pix=e&31;
        sh[e] = g_n2[((size_t)b*CH+ci)*HW + sp + pix];
    }
    __syncthreads();
    int pix = tid&31, g = tid>>5;
    int co0 = g*8;
    float acc[8];
    #pragma unroll
    for (int j=0;j<8;j++) acc[j] = __ldg(bias+co0+j);
    #pragma unroll 4
    for (int ci=0; ci<32; ci++){
        float v = sh[ci*32+pix];
        float4 wa = *(const float4*)&g_wn3T[ci*64+co0];
        float4 wb = *(const float4*)&g_wn3T[ci*64+co0+4];
        acc[0]+=v*wa.x; acc[1]+=v*wa.y; acc[2]+=v*wa.z; acc[3]+=v*wa.w;
        acc[4]+=v*wb.x; acc[5]+=v*wb.y; acc[6]+=v*wb.z; acc[7]+=v*wb.w;
    }
    #pragma unroll
    for (int j=0;j<8;j++){
        size_t o = ((size_t)b*64+co0+j)*HW + sp + pix;
        out[o] = x[o] + g_xr[o] + acc[j];
    }
}

// ---------------- launch ----------------
extern "C" void kernel_launch(void* const* d_in, const int* in_sizes, int n_in,
                              void* d_out, int out_size){
    const float* x     = (const float*)d_in[0];
    const float* w_off = (const float*)d_in[1];
    const float* b_off = (const float*)d_in[2];
    const float* w_dc  = (const float*)d_in[3];
    const float* b_dc  = (const float*)d_in[4];
    const float* w_ca1 = (const float*)d_in[5];
    const float* b_ca1 = (const float*)d_in[6];
    const float* w_ca2 = (const float*)d_in[7];
    const float* b_ca2 = (const float*)d_in[8];
    const float* w_sa  = (const float*)d_in[9];
    const float* b_sa  = (const float*)d_in[10];
    const float* w_r1  = (const float*)d_in[11];
    const float* b_r1  = (const float*)d_in[12];
    const float* w_r2  = (const float*)d_in[13];
    const float* b_r2  = (const float*)d_in[14];
    const float* w_n1  = (const float*)d_in[15];
    const float* b_n1  = (const float*)d_in[16];
    const float* w_n2  = (const float*)d_in[17];
    const float* b_n2  = (const float*)d_in[18];
    const float* w_n3  = (const float*)d_in[19];
    const float* b_n3  = (const float*)d_in[20];
    float* out = (float*)d_out;

    k_prep<<<256, 256>>>(w_off, w_dc, w_r2, w_r1, w_n1, w_n3);
    k_offmma<<<dim3(12, 24, Bn), 256>>>(x, b_off);
    k_deform_mma<<<1152, 256>>>(x, b_dc);
    k_mean<<<Bn*Cn, 256>>>();
    k_ca<<<Bn, 64>>>(w_ca1, b_ca1, w_ca2, b_ca2);
    k_saxa<<<dim3(Wn/32, Hn, Bn), 256>>>(w_sa, b_sa);
    k_r1mma<<<1152, 256>>>(b_r1);
    k_r2mma<<<dim3(12, 24, Bn), 256>>>(b_r2);
    k_n1<<<(Bn*HW)/32, 256>>>(b_n1);
    k_n2<<<(Bn*CH*HW + 255)/256, 256>>>(w_n2, b_n2);
    k_final<<<(Bn*HW)/32, 256>>>(x, b_n3, out);
}

// round 15
// speedup vs baseline: 5.2504x; 1.4135x over previous
#include <cuda_runtime.h>
#include <cuda_fp16.h>
#include <math.h>
#include <stdint.h>

#define Bn 4
#define Cn 64
#define Hn 192
#define Wn 192
#define HW (Hn*Wn)      // 36864
#define CM 256
#define CH 32

// ---------------- scratch (static device globals; no allocation) ----------------
__device__ float g_om  [Bn*27*HW];
__device__ float g_xd  [Bn*Cn*HW];
__device__ float g_mean[Bn*Cn];
__device__ float g_ca  [Bn*Cn];
__device__ float g_xr  [Bn*Cn*HW];
__device__ float g_n1  [Bn*CH*HW];
__device__ float g_n2  [Bn*CH*HW];
// half2-packed tensors (u32 = 2 fp16, channel pairs)
__device__ uint32_t g_xTh[Bn*HW*32];    // x transposed: [pix][ci2]  (NHWC half2)
__device__ uint32_t g_xah[Bn*32*HW];    // xa: [ci2][pix]
__device__ uint32_t g_t1h[Bn*128*HW];   // t1: [co2][pix]
// half2-packed weights: k pairs along cin
__device__ uint32_t g_woffH[32*288];    // [co pad32][tap*32 + ci2]
__device__ uint32_t g_wdcH [64*288];    // [co][tap*32 + ci2]
__device__ uint32_t g_wr1H [256*32];    // [co][ci2]
__device__ uint32_t g_wr2H [64*1152];   // [co][tap*128 + ci2]
__device__ float g_wn1T[64*32];
__device__ float g_wn3T[32*64];

__device__ __forceinline__ float sigmoidf_(float v){ return 1.f/(1.f+expf(-v)); }
__device__ __forceinline__ float leakyf_(float v){ return v >= 0.f ? v : 0.1f*v; }
__device__ __forceinline__ uint32_t packh2(float a, float b){
    __half2 h = __floats2half2_rn(a, b);
    return *(uint32_t*)&h;
}
__device__ __forceinline__ float2 unpackh2(uint32_t u){
    __half2 h = *(__half2*)&u;
    return __half22float2(h);
}
__device__ __forceinline__ void mma_f16(float* c, const uint32_t* a, const uint32_t* b){
    asm volatile("mma.sync.aligned.m16n8k16.row.col.f32.f16.f16.f32 "
        "{%0,%1,%2,%3}, {%4,%5,%6,%7}, {%8,%9}, {%0,%1,%2,%3};"
        : "+f"(c[0]), "+f"(c[1]), "+f"(c[2]), "+f"(c[3])
        : "r"(a[0]), "r"(a[1]), "r"(a[2]), "r"(a[3]), "r"(b[0]), "r"(b[1]));
}

// ---------------- weight packing ----------------
__global__ void k_prep(const float* __restrict__ woff, const float* __restrict__ wdc,
                       const float* __restrict__ wr2,  const float* __restrict__ wr1,
                       const float* __restrict__ wn1,  const float* __restrict__ wn3){
    int stride = gridDim.x*blockDim.x;
    int i0 = blockIdx.x*blockDim.x + threadIdx.x;
    for (int t=i0; t<32*288; t+=stride){
        int co = t/288; int k2 = t - co*288; int tap = k2>>5; int ci = (k2&31)*2;
        float a = (co<27) ? woff[co*576 + ci*9 + tap]     : 0.f;
        float b = (co<27) ? woff[co*576 + (ci+1)*9 + tap] : 0.f;
        g_woffH[t] = packh2(a, b);
    }
    for (int t=i0; t<64*288; t+=stride){
        int co = t/288; int k2 = t - co*288; int tap = k2>>5; int ci = (k2&31)*2;
        g_wdcH[t] = packh2(wdc[co*576 + ci*9 + tap], wdc[co*576 + (ci+1)*9 + tap]);
    }
    for (int t=i0; t<256*32; t+=stride){
        int co = t>>5; int ci = (t&31)*2;
        g_wr1H[t] = packh2(wr1[co*64+ci], wr1[co*64+ci+1]);
    }
    for (int t=i0; t<64*1152; t+=stride){
        int co = t/1152; int k2 = t - co*1152; int tap = k2>>7; int cin = (k2&127)*2;
        g_wr2H[t] = packh2(wr2[co*2304 + cin*9 + tap], wr2[co*2304 + (cin+1)*9 + tap]);
    }
    for (int t=i0; t<64*32; t+=stride){ int ci=t>>5, co=t&31; g_wn1T[t] = wn1[co*64 + ci]; }
    for (int t=i0; t<32*64; t+=stride){ int ci=t>>6, co=t&63; g_wn3T[t] = wn3[co*32 + ci]; }
}

// ---------------- x NCHW fp32 -> NHWC half2 ----------------
__global__ void __launch_bounds__(256) k_tr(const float* __restrict__ x){
    __shared__ uint32_t sm[128*33];
    int p0 = blockIdx.x*128;            // global pixel (batch-major)
    int b  = p0 / HW; int sp = p0 - b*HW;
    int tid = threadIdx.x;
    const float* xb = x + (size_t)b*Cn*HW + sp;
    #pragma unroll
    for (int it=0; it<16; it++){
        int id = tid + it*256;
        int p = id & 127, c2 = id >> 7;
        float f0 = __ldg(xb + (size_t)(2*c2)*HW + p);
        float f1 = __ldg(xb + (size_t)(2*c2+1)*HW + p);
        sm[p*33 + c2] = packh2(f0, f1);
    }
    __syncthreads();
    #pragma unroll
    for (int it=0; it<16; it++){
        int id = tid + it*256;
        int pix = id >> 5, c2 = id & 31;
        g_xTh[(size_t)(p0+pix)*32 + c2] = sm[pix*33 + c2];
    }
}

// ---------------- offset conv (fp16 halo mma): 27(pad32) <- 64x3x3 ----------------
__global__ void __launch_bounds__(256) k_offmma(const float* __restrict__ bias){
    __shared__ uint32_t Ahu[180*20];
    __shared__ uint32_t Bsu[2][32*20];
    int X0 = blockIdx.x*16, Y0 = blockIdx.y*8, b = blockIdx.z;
    int tid = threadIdx.x;
    int lane = tid & 31, warp = tid >> 5;
    int g = lane >> 2, t = lane & 3;

    const uint32_t* xTb = g_xTh + (size_t)b*HW*32;

    float acc[4][4];
    #pragma unroll
    for (int ni=0;ni<4;ni++)
        #pragma unroll
        for (int j=0;j<4;j++) acc[ni][j] = 0.f;

    for (int cb = 0; cb < 2; cb++){
        __syncthreads();
        for (int id = tid; id < 2880; id += 256){
            int pk = id >> 4, c2 = id & 15;
            int hy = pk/18, hx = pk - hy*18;
            int gy = Y0 + hy - 1, gx = X0 + hx - 1;
            uint32_t v = 0u;
            if ((unsigned)gy < (unsigned)Hn && (unsigned)gx < (unsigned)Wn)
                v = __ldg(xTb + (size_t)(gy*Wn+gx)*32 + cb*16 + c2);
            Ahu[pk*20 + c2] = v;
        }
        // stage B tap0 -> buf0 : 32 co x 16 u32 = 512 tasks (2 iters of 256)
        #pragma unroll
        for (int it = 0; it < 2; it++){
            int id = tid + it*256;
            int co = id >> 4, c2 = id & 15;
            Bsu[0][co*20 + c2] = g_woffH[co*288 + cb*16 + c2];
        }
        for (int tap = 0; tap < 9; tap++){
            __syncthreads();
            if (tap < 8){
                #pragma unroll
                for (int it = 0; it < 2; it++){
                    int id = tid + it*256;
                    int co = id >> 4, c2 = id & 15;
                    Bsu[(tap+1)&1][co*20 + c2] = g_woffH[co*288 + (tap+1)*32 + cb*16 + c2];
                }
            }
            const uint32_t* B = Bsu[tap&1];
            int toff = (tap/3)*18 + tap - (tap/3)*3;
            int hh = warp*18 + g + toff;
            #pragma unroll
            for (int kc = 0; kc < 2; kc++){
                uint32_t a[4], bb[4][2];
                a[0] = Ahu[hh*20 + kc*8 + t];
                a[1] = Ahu[(hh+8)*20 + kc*8 + t];
                a[2] = Ahu[hh*20 + kc*8 + t + 4];
                a[3] = Ahu[(hh+8)*20 + kc*8 + t + 4];
                #pragma unroll
                for (int ni=0;ni<4;ni++){
                    int cN = ni*8 + g;
                    bb[ni][0] = B[cN*20 + kc*8 + t];
                    bb[ni][1] = B[cN*20 + kc*8 + t + 4];
                }
                #pragma unroll
                for (int ni=0;ni<4;ni++)
                    mma_f16(acc[ni], a, bb[ni]);
            }
        }
    }
    int yy = Y0 + warp;
    float* omb = g_om + (size_t)b*27*HW;
    int q0 = yy*Wn + X0 + g;
    #pragma unroll
    for (int ni=0;ni<4;ni++){
        int cN = ni*8 + 2*t;
        #pragma unroll
        for (int u=0;u<2;u++){
            int c = cN + u;
            if (c < 27){
                float bb = __ldg(bias + c);
                float v0 = leakyf_(acc[ni][u]   + bb);
                float v1 = leakyf_(acc[ni][2+u] + bb);
                if (c >= 18){ v0 = sigmoidf_(v0); v1 = sigmoidf_(v1); }
                omb[(size_t)c*HW + q0    ] = v0;
                omb[(size_t)c*HW + q0 + 8] = v1;
            }
        }
    }
}

// ---------------- deformable conv (fp16 mma, NHWC gather) ----------------
__global__ void __launch_bounds__(256) k_deform_mma(const float* __restrict__ bias){
    __shared__ uint32_t As[128*20];
    __shared__ uint32_t Bs[64*20];
    __shared__ float cw4[4][128];
    __shared__ int   ci4[4][128];
    int tile = blockIdx.x;
    int b  = tile / 288;
    int pp0 = (tile - b*288) * 128;
    int tid = threadIdx.x;
    int lane = tid & 31, warp = tid >> 5;
    int m0 = (warp & 3) * 32;
    int n0 = (warp >> 2) * 32;
    int g = lane >> 2, t = lane & 3;

    const uint32_t* xTb = g_xTh + (size_t)b*HW*32;

    float acc[2][4][4];
    #pragma unroll
    for (int mi=0;mi<2;mi++)
        #pragma unroll
        for (int ni=0;ni<4;ni++)
            #pragma unroll
            for (int j=0;j<4;j++) acc[mi][ni][j] = 0.f;

    for (int j = 0; j < 18; j++){
        int tap = j >> 1;
        int hf  = j & 1;
        __syncthreads();
        if (hf == 0 && tid < 128){
            int pix = tid;
            int pp = pp0 + pix;
            int gy = pp / Wn, gx = pp - (pp/Wn)*Wn;
            float dyv = g_om[((size_t)b*27 + 2*tap  )*HW + pp];
            float dxv = g_om[((size_t)b*27 + 2*tap+1)*HW + pp];
            float m   = g_om[((size_t)b*27 + 18+tap )*HW + pp];
            float py = (float)gy + (float)(tap/3 - 1) + dyv;
            float px = (float)gx + (float)(tap%3 - 1) + dxv;
            float fy = floorf(py), fx = floorf(px);
            int y0 = (int)fy, xq = (int)fx;
            float wy = py - fy, wx = px - fx;
            int y1 = y0+1, x1 = xq+1;
            int yc0 = min(max(y0,0),Hn-1), yc1 = min(max(y1,0),Hn-1);
            int xc0 = min(max(xq,0),Wn-1), xc1 = min(max(x1,0),Wn-1);
            float vy0 = (y0>=0 && y0<Hn)?1.f:0.f;
            float vy1 = (y1>=0 && y1<Hn)?1.f:0.f;
            float vx0 = (xq>=0 && xq<Wn)?1.f:0.f;
            float vx1 = (x1>=0 && x1<Wn)?1.f:0.f;
            cw4[0][pix] = (1.f-wy)*(1.f-wx)*vy0*vx0*m;  ci4[0][pix] = yc0*Wn+xc0;
            cw4[1][pix] = (1.f-wy)*wx     *vy0*vx1*m;   ci4[1][pix] = yc0*Wn+xc1;
            cw4[2][pix] = wy     *(1.f-wx)*vy1*vx0*m;   ci4[2][pix] = yc1*Wn+xc0;
            cw4[3][pix] = wy     *wx      *vy1*vx1*m;   ci4[3][pix] = yc1*Wn+xc1;
        }
        __syncthreads();
        // stage A: 128 pix x 16 u32 gathered from NHWC half2
        #pragma unroll
        for (int it = 0; it < 8; it++){
            int id = tid + it*256;
            int c2 = id & 15, pix = id >> 4;
            int cc = hf*16 + c2;
            float w0 = cw4[0][pix], w1 = cw4[1][pix], w2 = cw4[2][pix], w3 = cw4[3][pix];
            float2 f0 = unpackh2(__ldg(xTb + (size_t)ci4[0][pix]*32 + cc));
            float2 f1 = unpackh2(__ldg(xTb + (size_t)ci4[1][pix]*32 + cc));
            float2 f2 = unpackh2(__ldg(xTb + (size_t)ci4[2][pix]*32 + cc));
            float2 f3 = unpackh2(__ldg(xTb + (size_t)ci4[3][pix]*32 + cc));
            float sx = w0*f0.x + w1*f1.x + w2*f2.x + w3*f3.x;
            float sy = w0*f0.y + w1*f1.y + w2*f2.y + w3*f3.y;
            As[pix*20 + c2] = packh2(sx, sy);
        }
        // stage B: 64 co x 16 u32 = 1024 tasks
        #pragma unroll
        for (int it = 0; it < 4; it++){
            int id = tid + it*256;
            int co = id >> 4, c2 = id & 15;
            Bs[co*20 + c2] = g_wdcH[co*288 + tap*32 + hf*16 + c2];
        }
        __syncthreads();
        #pragma unroll
        for (int kc = 0; kc < 2; kc++){
            uint32_t afr[2][4], bfr[4][2];
            #pragma unroll
            for (int mi=0;mi<2;mi++){
                int r = m0 + mi*16;
                afr[mi][0] = As[(r+g  )*20 + kc*8 + t];
                afr[mi][1] = As[(r+g+8)*20 + kc*8 + t];
                afr[mi][2] = As[(r+g  )*20 + kc*8 + t + 4];
                afr[mi][3] = As[(r+g+8)*20 + kc*8 + t + 4];
            }
            #pragma unroll
            for (int ni=0;ni<4;ni++){
                int cN = n0 + ni*8 + g;
                bfr[ni][0] = Bs[cN*20 + kc*8 + t];
                bfr[ni][1] = Bs[cN*20 + kc*8 + t + 4];
            }
            #pragma unroll
            for (int mi=0;mi<2;mi++)
                #pragma unroll
                for (int ni=0;ni<4;ni++)
                    mma_f16(acc[mi][ni], afr[mi], bfr[ni]);
        }
    }
    float* xdb = g_xd + (size_t)b*Cn*HW + pp0;
    #pragma unroll
    for (int mi=0;mi<2;mi++){
        int row = m0 + mi*16 + g;
        #pragma unroll
        for (int ni=0;ni<4;ni++){
            int col = n0 + ni*8 + 2*t;
            float b0 = __ldg(bias + col), b1 = __ldg(bias + col + 1);
            xdb[(size_t)col*HW     + row    ] = acc[mi][ni][0] + b0;
            xdb[(size_t)(col+1)*HW + row    ] = acc[mi][ni][1] + b1;
            xdb[(size_t)col*HW     + row + 8] = acc[mi][ni][2] + b0;
            xdb[(size_t)(col+1)*HW + row + 8] = acc[mi][ni][3] + b1;
        }
    }
}

// ---------------- channel mean ----------------
__global__ void __launch_bounds__(256) k_mean(){
    int bc = blockIdx.x;
    const float* p = g_xd + (size_t)bc*HW;
    float s = 0.f;
    for (int i=threadIdx.x; i<HW; i+=256) s += p[i];
    __shared__ float red[256];
    red[threadIdx.x] = s; __syncthreads();
    for (int o=128; o>0; o>>=1){
        if (threadIdx.x < o) red[threadIdx.x] += red[threadIdx.x+o];
        __syncthreads();
    }
    if (threadIdx.x==0) g_mean[bc] = red[0]*(1.f/HW);
}

// ---------------- channel attention MLP ----------------
__global__ void k_ca(const float* __restrict__ w1, const float* __restrict__ b1,
                     const float* __restrict__ w2, const float* __restrict__ b2){
    int b = blockIdx.x; int t = threadIdx.x;
    __shared__ float mn[64], h[8];
    mn[t] = g_mean[b*64+t];
    __syncthreads();
    if (t < 8){
        float s = __ldg(b1+t);
        for (int c=0;c<64;c++) s += __ldg(w1+t*64+c)*mn[c];
        h[t] = s > 0.f ? s : 0.f;
    }
    __syncthreads();
    float s = __ldg(b2+t);
    #pragma unroll
    for (int j=0;j<8;j++) s += __ldg(w2+t*8+j)*h[j];
    g_ca[b*64+t] = sigmoidf_(s);
}

// ---------------- spatial attention + xa (half2 out) ----------------
__global__ void __launch_bounds__(256) k_saxa(const float* __restrict__ wsa,
                                              const float* __restrict__ bsa){
    __shared__ float sh[64*102];
    __shared__ float part[8][32];
    __shared__ float sav[32];
    int x0 = blockIdx.x*32, y = blockIdx.y, b = blockIdx.z;
    int tid = threadIdx.x;
    const float* xb = g_xd + (size_t)b*Cn*HW;
    for (int e=tid; e<64*102; e+=256){
        int ci = e/102; int r = e%102; int dy = r/34; int xx = r%34;
        int gy = y+dy-1, gx = x0+xx-1;
        sh[e] = (gy>=0 && gy<Hn && gx>=0 && gx<Wn) ? xb[ci*HW + gy*Wn + gx] : 0.f;
    }
    __syncthreads();
    int pix = tid&31, g = tid>>5;
    float acc = 0.f;
    for (int ci=g*8; ci<g*8+8; ci++){
        const float* s = sh + ci*102 + pix;
        const float* wp = wsa + ci*9;
        acc += s[0]*__ldg(wp+0) + s[1]*__ldg(wp+1) + s[2]*__ldg(wp+2)
             + s[34]*__ldg(wp+3) + s[35]*__ldg(wp+4) + s[36]*__ldg(wp+5)
             + s[68]*__ldg(wp+6) + s[69]*__ldg(wp+7) + s[70]*__ldg(wp+8);
    }
    part[g][pix] = acc;
    __syncthreads();
    if (g == 0){
        float t = __ldg(bsa);
        #pragma unroll
        for (int j=0;j<8;j++) t += part[j][pix];
        sav[pix] = sigmoidf_(t);
    }
    __syncthreads();
    float sa = sav[pix];
    #pragma unroll
    for (int j=0;j<4;j++){
        int co2 = g + j*8;
        int co  = co2*2;
        float v0 = sh[co*102     + 34 + pix + 1];
        float v1 = sh[(co+1)*102 + 34 + pix + 1];
        float a0 = v0 * (g_ca[b*64+co]   + sa);
        float a1 = v1 * (g_ca[b*64+co+1] + sa);
        g_xah[((size_t)b*32+co2)*HW + y*Wn + x0 + pix] = packh2(a0, a1);
    }
}

// ---------------- r1 (fp16 mma): 1x1 64->256, leaky, half2 out ----------------
__global__ void __launch_bounds__(256) k_r1mma(const float* __restrict__ bias){
    __shared__ uint32_t Asu[128*36];
    __shared__ uint32_t Bsu[64*36];
    int tile = blockIdx.x;
    int b  = tile / 288;
    int pp0 = (tile - b*288) * 128;
    int tid = threadIdx.x;
    int lane = tid & 31, warp = tid >> 5;
    int m0 = (warp & 3) * 32;
    int n0 = (warp >> 2) * 32;
    int g = lane >> 2, t = lane & 3;

    const uint32_t* xab = g_xah + (size_t)b*32*HW;

    // stage full A once: 128 pix x 32 u32
    #pragma unroll
    for (int it = 0; it < 16; it++){
        int id = tid + it*256;
        int pix = id & 127, c2 = id >> 7;
        Asu[pix*36 + c2] = __ldg(xab + (size_t)c2*HW + pp0 + pix);
    }

    for (int cob = 0; cob < 4; cob++){
        float acc[2][4][4];
        #pragma unroll
        for (int mi=0;mi<2;mi++)
            #pragma unroll
            for (int ni=0;ni<4;ni++)
                #pragma unroll
                for (int j=0;j<4;j++) acc[mi][ni][j] = 0.f;
        __syncthreads();
        #pragma unroll
        for (int it = 0; it < 8; it++){
            int id = tid + it*256;
            int co = id >> 5, c2 = id & 31;
            Bsu[co*36 + c2] = g_wr1H[(size_t)(cob*64+co)*32 + c2];
        }
        __syncthreads();
        #pragma unroll
        for (int kc = 0; kc < 4; kc++){
            uint32_t afr[2][4], bfr[4][2];
            #pragma unroll
            for (int mi=0;mi<2;mi++){
                int r = m0 + mi*16;
                afr[mi][0] = Asu[(r+g  )*36 + kc*8 + t];
                afr[mi][1] = Asu[(r+g+8)*36 + kc*8 + t];
                afr[mi][2] = Asu[(r+g  )*36 + kc*8 + t + 4];
                afr[mi][3] = Asu[(r+g+8)*36 + kc*8 + t + 4];
            }
            #pragma unroll
            for (int ni=0;ni<4;ni++){
                int cN = n0 + ni*8 + g;
                bfr[ni][0] = Bsu[cN*36 + kc*8 + t];
                bfr[ni][1] = Bsu[cN*36 + kc*8 + t + 4];
            }
            #pragma unroll
            for (int mi=0;mi<2;mi++)
                #pragma unroll
                for (int ni=0;ni<4;ni++)
                    mma_f16(acc[mi][ni], afr[mi], bfr[ni]);
        }
        uint32_t* t1b = g_t1h + (size_t)b*128*HW + pp0;
        #pragma unroll
        for (int mi=0;mi<2;mi++){
            int row = m0 + mi*16 + g;
            #pragma unroll
            for (int ni=0;ni<4;ni++){
                int col = cob*64 + n0 + ni*8 + 2*t;
                int co2 = col >> 1;
                float b0 = __ldg(bias + col), b1 = __ldg(bias + col + 1);
                t1b[(size_t)co2*HW + row    ] = packh2(leakyf_(acc[mi][ni][0]+b0),
                                                       leakyf_(acc[mi][ni][1]+b1));
                t1b[(size_t)co2*HW + row + 8] = packh2(leakyf_(acc[mi][ni][2]+b0),
                                                       leakyf_(acc[mi][ni][3]+b1));
            }
        }
    }
}

// ---------------- r2 (fp16 halo mma): 3x3 256->64 ----------------
__global__ void __launch_bounds__(256) k_r2mma(const float* __restrict__ bias){
    __shared__ uint32_t Ahu[180*20];
    __shared__ uint32_t Bsu[2][64*20];
    int X0 = blockIdx.x*16, Y0 = blockIdx.y*8, b = blockIdx.z;
    int tid = threadIdx.x;
    int lane = tid & 31, warp = tid >> 5;
    int m0 = (warp & 3) * 32;
    int n0 = (warp >> 2) * 32;
    int g = lane >> 2, t = lane & 3;
    int hb0 = (m0 >> 4)*18 + g;

    const uint32_t* t1b = g_t1h + (size_t)b*128*HW;

    float acc[2][4][4];
    #pragma unroll
    for (int mi=0;mi<2;mi++)
        #pragma unroll
        for (int ni=0;ni<4;ni++)
            #pragma unroll
            for (int j=0;j<4;j++) acc[mi][ni][j] = 0.f;

    for (int cb = 0; cb < 8; cb++){
        __syncthreads();
        // stage halo: 180 px x 16 u32, pk-fastest (coalesced over pixels)
        for (int id = tid; id < 2880; id += 256){
            int c2 = id / 180, pk = id - c2*180;
            int hy = pk/18, hx = pk - hy*18;
            int gy = Y0 + hy - 1, gx = X0 + hx - 1;
            uint32_t v = 0u;
            if ((unsigned)gy < (unsigned)Hn && (unsigned)gx < (unsigned)Wn)
                v = __ldg(t1b + (size_t)(cb*16 + c2)*HW + gy*Wn + gx);
            Ahu[pk*20 + c2] = v;
        }
        #pragma unroll
        for (int it = 0; it < 4; it++){
            int id = tid + it*256;
            int co = id >> 4, c2 = id & 15;
            Bsu[0][co*20 + c2] = g_wr2H[(size_t)co*1152 + cb*16 + c2];
        }
        for (int tap = 0; tap < 9; tap++){
            __syncthreads();
            if (tap < 8){
                #pragma unroll
                for (int it = 0; it < 4; it++){
                    int id = tid + it*256;
                    int co = id >> 4, c2 = id & 15;
                    Bsu[(tap+1)&1][co*20 + c2] =
                        g_wr2H[(size_t)co*1152 + (tap+1)*128 + cb*16 + c2];
                }
            }
            const uint32_t* B = Bsu[tap&1];
            int toff = (tap/3)*18 + tap - (tap/3)*3;
            #pragma unroll
            for (int kc = 0; kc < 2; kc++){
                uint32_t afr[2][4], bfr[4][2];
                #pragma unroll
                for (int mi=0;mi<2;mi++){
                    int hh = hb0 + mi*18 + toff;
                    afr[mi][0] = Ahu[hh*20 + kc*8 + t];
                    afr[mi][1] = Ahu[(hh+8)*20 + kc*8 + t];
                    afr[mi][2] = Ahu[hh*20 + kc*8 + t + 4];
                    afr[mi][3] = Ahu[(hh+8)*20 + kc*8 + t + 4];
                }
                #pragma unroll
                for (int ni=0;ni<4;ni++){
                    int cN = n0 + ni*8 + g;
                    bfr[ni][0] = B[cN*20 + kc*8 + t];
                    bfr[ni][1] = B[cN*20 + kc*8 + t + 4];
                }
                #pragma unroll
                for (int mi=0;mi<2;mi++)
                    #pragma unroll
                    for (int ni=0;ni<4;ni++)
                        mma_f16(acc[mi][ni], afr[mi], bfr[ni]);
            }
        }
    }
    float* xrb = g_xr + (size_t)b*Cn*HW;
    int ybase = Y0 + (m0 >> 4);
    #pragma unroll
    for (int mi=0;mi<2;mi++){
        int q0 = (ybase + mi)*Wn + X0 + g;
        #pragma unroll
        for (int ni=0;ni<4;ni++){
            int col = n0 + ni*8 + 2*t;
            float b0 = __ldg(bias + col), b1 = __ldg(bias + col + 1);
            xrb[(size_t)col*HW     + q0    ] = acc[mi][ni][0] + b0;
            xrb[(size_t)(col+1)*HW + q0    ] = acc[mi][ni][1] + b1;
            xrb[(size_t)col*HW     + q0 + 8] = acc[mi][ni][2] + b0;
            xrb[(size_t)(col+1)*HW + q0 + 8] = acc[mi][ni][3] + b1;
        }
    }
}

// ---------------- n1: 1x1, 64 -> 32 (reads half2 xa) ----------------
__global__ void __launch_bounds__(256) k_n1(const float* __restrict__ bias){
    __shared__ uint32_t shu[32*32];
    int p0 = blockIdx.x*32; int b = p0/HW; int sp = p0%HW;
    int tid = threadIdx.x;
    for (int e=tid; e<1024; e+=256){
        int c2 = e>>5, pix = e&31;
        shu[e] = __ldg(g_xah + ((size_t)b*32+c2)*HW + sp + pix);
    }
    __syncthreads();
    int pix = tid&31, g = tid>>5;
    int co0 = g*4;
    float acc[4];
    #pragma unroll
    for (int j=0;j<4;j++) acc[j] = __ldg(bias+co0+j);
    #pragma unroll 8
    for (int c2=0; c2<32; c2++){
        float2 f = unpackh2(shu[c2*32+pix]);
        int ci = 2*c2;
        #pragma unroll
        for (int j=0;j<4;j++)
            acc[j] += f.x*__ldg(&g_wn1T[ci*32+co0+j]) + f.y*__ldg(&g_wn1T[(ci+1)*32+co0+j]);
    }
    #pragma unroll
    for (int j=0;j<4;j++)
        g_n1[((size_t)b*CH+co0+j)*HW + sp + pix] = acc[j];
}

// ---------------- n2: depthwise 3x3 ----------------
__global__ void __launch_bounds__(256) k_n2(const float* __restrict__ w,
                                            const float* __restrict__ bias){
    int idx = blockIdx.x*256 + threadIdx.x;
    if (idx >= Bn*CH*HW) return;
    int pp = idx % HW; int bc = idx / HW; int c = bc % CH;
    int gy = pp/Wn, gx = pp%Wn;
    const float* in = g_n1 + (size_t)bc*HW;
    float acc = __ldg(bias+c);
    #pragma unroll
    for (int ky=0;ky<3;ky++){
        int yy = gy+ky-1;
        if (yy<0 || yy>=Hn) continue;
        #pragma unroll
        for (int kx=0;kx<3;kx++){
            int xx = gx+kx-1;
            if (xx<0 || xx>=Wn) continue;
            acc += in[yy*Wn+xx]*__ldg(w + c*9 + ky*3 + kx);
        }
    }
    g_n2[idx] = acc;
}

// ---------------- final: out = x + xr + (1x1 32->64)(n2) ----------------
__global__ void __launch_bounds__(256) k_final(const float* __restrict__ x,
                                               const float* __restrict__ bias,
                                               float* __restrict__ out){
    __shared__ float sh[32*32];
    int p0 = blockIdx.x*32; int b = p0/HW; int sp = p0%HW;
    int tid = threadIdx.x;
    for (int e=tid; e<32*32; e+=256){
        int ci=e>>5, pix=e&31;
        sh[e] = g_n2[((size_t)b*CH+ci)*HW + sp + pix];
    }
    __syncthreads();
    int pix = tid&31, g = tid>>5;
    int co0 = g*8;
    float acc[8];
    #pragma unroll
    for (int j=0;j<8;j++) acc[j] = __ldg(bias+co0+j);
    #pragma unroll 4
    for (int ci=0; ci<32; ci++){
        float v = sh[ci*32+pix];
        float4 wa = *(const float4*)&g_wn3T[ci*64+co0];
        float4 wb = *(const float4*)&g_wn3T[ci*64+co0+4];
        acc[0]+=v*wa.x; acc[1]+=v*wa.y; acc[2]+=v*wa.z; acc[3]+=v*wa.w;
        acc[4]+=v*wb.x; acc[5]+=v*wb.y; acc[6]+=v*wb.z; acc[7]+=v*wb.w;
    }
    #pragma unroll
    for (int j=0;j<8;j++){
        size_t o = ((size_t)b*64+co0+j)*HW + sp + pix;
        out[o] = x[o] + g_xr[o] + acc[j];
    }
}

// ---------------- launch ----------------
extern "C" void kernel_launch(void* const* d_in, const int* in_sizes, int n_in,
                              void* d_out, int out_size){
    const float* x     = (const float*)d_in[0];
    const float* w_off = (const float*)d_in[1];
    const float* b_off = (const float*)d_in[2];
    const float* w_dc  = (const float*)d_in[3];
    const float* b_dc  = (const float*)d_in[4];
    const float* w_ca1 = (const float*)d_in[5];
    const float* b_ca1 = (const float*)d_in[6];
    const float* w_ca2 = (const float*)d_in[7];
    const float* b_ca2 = (const float*)d_in[8];
    const float* w_sa  = (const float*)d_in[9];
    const float* b_sa  = (const float*)d_in[10];
    const float* w_r1  = (const float*)d_in[11];
    const float* b_r1  = (const float*)d_in[12];
    const float* w_r2  = (const float*)d_in[13];
    const float* b_r2  = (const float*)d_in[14];
    const float* w_n1  = (const float*)d_in[15];
    const float* b_n1  = (const float*)d_in[16];
    const float* w_n2  = (const float*)d_in[17];
    const float* b_n2  = (const float*)d_in[18];
    const float* w_n3  = (const float*)d_in[19];
    const float* b_n3  = (const float*)d_in[20];
    float* out = (float*)d_out;

    k_prep<<<256, 256>>>(w_off, w_dc, w_r2, w_r1, w_n1, w_n3);
    k_tr<<<(Bn*HW)/128, 256>>>(x);
    k_offmma<<<dim3(12, 24, Bn), 256>>>(b_off);
    k_deform_mma<<<1152, 256>>>(b_dc);
    k_mean<<<Bn*Cn, 256>>>();
    k_ca<<<Bn, 64>>>(w_ca1, b_ca1, w_ca2, b_ca2);
    k_saxa<<<dim3(Wn/32, Hn, Bn), 256>>>(w_sa, b_sa);
    k_r1mma<<<1152, 256>>>(b_r1);
    k_r2mma<<<dim3(12, 24, Bn), 256>>>(b_r2);
    k_n1<<<(Bn*HW)/32, 256>>>(b_n1);
    k_n2<<<(Bn*CH*HW + 255)/256, 256>>>(w_n2, b_n2);
    k_final<<<(Bn*HW)/32, 256>>>(x, b_n3, out);
}

// round 16
// speedup vs baseline: 6.8098x; 1.2970x over previous
#include <cuda_runtime.h>
#include <cuda_fp16.h>
#include <math.h>
#include <stdint.h>

#define Bn 4
#define Cn 64
#define Hn 192
#define Wn 192
#define HW (Hn*Wn)      // 36864
#define CM 256
#define CH 32

// ---------------- scratch (static device globals; no allocation) ----------------
__device__ float g_om  [Bn*27*HW];
__device__ float g_xd  [Bn*Cn*HW];
__device__ float g_mean[Bn*Cn];
__device__ float g_ca  [Bn*Cn];
__device__ float g_xr  [Bn*Cn*HW];
__device__ float g_n1  [Bn*CH*HW];
__device__ float g_n2  [Bn*CH*HW];
// half2-packed tensors (u32 = 2 fp16, channel pairs)
__device__ __align__(16) uint32_t g_xTh[Bn*HW*32];    // x transposed: [pix][ci2]  (NHWC half2)
__device__ __align__(16) uint32_t g_xah[Bn*32*HW];    // xa: [ci2][pix]
__device__ __align__(16) uint32_t g_t1h[Bn*128*HW];   // t1: [co2][pix]
// half2-packed weights: k pairs along cin
__device__ __align__(16) uint32_t g_woffH[32*288];    // [co pad32][tap*32 + ci2]
__device__ __align__(16) uint32_t g_wdcH [64*288];    // [co][tap*32 + ci2]
__device__ __align__(16) uint32_t g_wr1H [256*32];    // [co][ci2]
__device__ __align__(16) uint32_t g_wr2H [64*1152];   // [co][tap*128 + ci2]
__device__ float g_wn1T[64*32];
__device__ float g_wn3T[32*64];

__device__ __forceinline__ float sigmoidf_(float v){ return 1.f/(1.f+expf(-v)); }
__device__ __forceinline__ float leakyf_(float v){ return v >= 0.f ? v : 0.1f*v; }
__device__ __forceinline__ uint32_t packh2(float a, float b){
    __half2 h = __floats2half2_rn(a, b);
    return *(uint32_t*)&h;
}
__device__ __forceinline__ float2 unpackh2(uint32_t u){
    __half2 h = *(__half2*)&u;
    return __half22float2(h);
}
__device__ __forceinline__ uint32_t bil4(uint32_t a, uint32_t b, uint32_t c, uint32_t d,
                                         float w0, float w1, float w2, float w3){
    float2 f0 = unpackh2(a), f1 = unpackh2(b), f2 = unpackh2(c), f3 = unpackh2(d);
    return packh2(w0*f0.x + w1*f1.x + w2*f2.x + w3*f3.x,
                  w0*f0.y + w1*f1.y + w2*f2.y + w3*f3.y);
}
__device__ __forceinline__ void mma_f16(float* c, const uint32_t* a, const uint32_t* b){
    asm volatile("mma.sync.aligned.m16n8k16.row.col.f32.f16.f16.f32 "
        "{%0,%1,%2,%3}, {%4,%5,%6,%7}, {%8,%9}, {%0,%1,%2,%3};"
        : "+f"(c[0]), "+f"(c[1]), "+f"(c[2]), "+f"(c[3])
        : "r"(a[0]), "r"(a[1]), "r"(a[2]), "r"(a[3]), "r"(b[0]), "r"(b[1]));
}

// ---------------- weight packing ----------------
__global__ void k_prep(const float* __restrict__ woff, const float* __restrict__ wdc,
                       const float* __restrict__ wr2,  const float* __restrict__ wr1,
                       const float* __restrict__ wn1,  const float* __restrict__ wn3){
    int stride = gridDim.x*blockDim.x;
    int i0 = blockIdx.x*blockDim.x + threadIdx.x;
    for (int t=i0; t<32*288; t+=stride){
        int co = t/288; int k2 = t - co*288; int tap = k2>>5; int ci = (k2&31)*2;
        float a = (co<27) ? woff[co*576 + ci*9 + tap]     : 0.f;
        float b = (co<27) ? woff[co*576 + (ci+1)*9 + tap] : 0.f;
        g_woffH[t] = packh2(a, b);
    }
    for (int t=i0; t<64*288; t+=stride){
        int co = t/288; int k2 = t - co*288; int tap = k2>>5; int ci = (k2&31)*2;
        g_wdcH[t] = packh2(wdc[co*576 + ci*9 + tap], wdc[co*576 + (ci+1)*9 + tap]);
    }
    for (int t=i0; t<256*32; t+=stride){
        int co = t>>5; int ci = (t&31)*2;
        g_wr1H[t] = packh2(wr1[co*64+ci], wr1[co*64+ci+1]);
    }
    for (int t=i0; t<64*1152; t+=stride){
        int co = t/1152; int k2 = t - co*1152; int tap = k2>>7; int cin = (k2&127)*2;
        g_wr2H[t] = packh2(wr2[co*2304 + cin*9 + tap], wr2[co*2304 + (cin+1)*9 + tap]);
    }
    for (int t=i0; t<64*32; t+=stride){ int ci=t>>5, co=t&31; g_wn1T[t] = wn1[co*64 + ci]; }
    for (int t=i0; t<32*64; t+=stride){ int ci=t>>6, co=t&63; g_wn3T[t] = wn3[co*32 + ci]; }
}

// ---------------- x NCHW fp32 -> NHWC half2 ----------------
__global__ void __launch_bounds__(256) k_tr(const float* __restrict__ x){
    __shared__ uint32_t sm[128*33];
    int p0 = blockIdx.x*128;
    int b  = p0 / HW; int sp = p0 - b*HW;
    int tid = threadIdx.x;
    const float* xb = x + (size_t)b*Cn*HW + sp;
    #pragma unroll
    for (int it=0; it<16; it++){
        int id = tid + it*256;
        int p = id & 127, c2 = id >> 7;
        float f0 = __ldg(xb + (size_t)(2*c2)*HW + p);
        float f1 = __ldg(xb + (size_t)(2*c2+1)*HW + p);
        sm[p*33 + c2] = packh2(f0, f1);
    }
    __syncthreads();
    #pragma unroll
    for (int it=0; it<16; it++){
        int id = tid + it*256;
        int pix = id >> 5, c2 = id & 31;
        g_xTh[(size_t)(p0+pix)*32 + c2] = sm[pix*33 + c2];
    }
}

// ---------------- offset conv (fp16 halo mma): 27(pad32) <- 64x3x3 ----------------
__global__ void __launch_bounds__(256) k_offmma(const float* __restrict__ bias){
    __shared__ uint32_t Ahu[180*20];
    __shared__ __align__(16) uint32_t Bsu[2][32*20];
    int X0 = blockIdx.x*16, Y0 = blockIdx.y*8, b = blockIdx.z;
    int tid = threadIdx.x;
    int lane = tid & 31, warp = tid >> 5;
    int g = lane >> 2, t = lane & 3;

    const uint32_t* xTb = g_xTh + (size_t)b*HW*32;

    float acc[4][4];
    #pragma unroll
    for (int ni=0;ni<4;ni++)
        #pragma unroll
        for (int j=0;j<4;j++) acc[ni][j] = 0.f;

    for (int cb = 0; cb < 2; cb++){
        __syncthreads();
        for (int id = tid; id < 2880; id += 256){
            int pk = id >> 4, c2 = id & 15;
            int hy = pk/18, hx = pk - hy*18;
            int gy = Y0 + hy - 1, gx = X0 + hx - 1;
            uint32_t v = 0u;
            if ((unsigned)gy < (unsigned)Hn && (unsigned)gx < (unsigned)Wn)
                v = __ldg(xTb + (size_t)(gy*Wn+gx)*32 + cb*16 + c2);
            Ahu[pk*20 + c2] = v;
        }
        // stage B tap0 -> buf0 : 32 co x 4 quads = 128 tasks
        if (tid < 128){
            int co = tid >> 2, q = tid & 3;
            *(uint4*)&Bsu[0][co*20 + q*4] =
                __ldg((const uint4*)(g_woffH + co*288 + cb*16) + q);
        }
        for (int tap = 0; tap < 9; tap++){
            __syncthreads();
            if (tap < 8 && tid < 128){
                int co = tid >> 2, q = tid & 3;
                *(uint4*)&Bsu[(tap+1)&1][co*20 + q*4] =
                    __ldg((const uint4*)(g_woffH + co*288 + (tap+1)*32 + cb*16) + q);
            }
            const uint32_t* B = Bsu[tap&1];
            int toff = (tap/3)*18 + tap - (tap/3)*3;
            int hh = warp*18 + g + toff;
            #pragma unroll
            for (int kc = 0; kc < 2; kc++){
                uint32_t a[4], bb[4][2];
                a[0] = Ahu[hh*20 + kc*8 + t];
                a[1] = Ahu[(hh+8)*20 + kc*8 + t];
                a[2] = Ahu[hh*20 + kc*8 + t + 4];
                a[3] = Ahu[(hh+8)*20 + kc*8 + t + 4];
                #pragma unroll
                for (int ni=0;ni<4;ni++){
                    int cN = ni*8 + g;
                    bb[ni][0] = B[cN*20 + kc*8 + t];
                    bb[ni][1] = B[cN*20 + kc*8 + t + 4];
                }
                #pragma unroll
                for (int ni=0;ni<4;ni++)
                    mma_f16(acc[ni], a, bb[ni]);
            }
        }
    }
    int yy = Y0 + warp;
    float* omb = g_om + (size_t)b*27*HW;
    int q0 = yy*Wn + X0 + g;
    #pragma unroll
    for (int ni=0;ni<4;ni++){
        int cN = ni*8 + 2*t;
        #pragma unroll
        for (int u=0;u<2;u++){
            int c = cN + u;
            if (c < 27){
                float bb = __ldg(bias + c);
                float v0 = leakyf_(acc[ni][u]   + bb);
                float v1 = leakyf_(acc[ni][2+u] + bb);
                if (c >= 18){ v0 = sigmoidf_(v0); v1 = sigmoidf_(v1); }
                omb[(size_t)c*HW + q0    ] = v0;
                omb[(size_t)c*HW + q0 + 8] = v1;
            }
        }
    }
}

// ---------------- deformable conv (fp16 mma, uint4 NHWC gather) ----------------
__global__ void __launch_bounds__(256) k_deform_mma(const float* __restrict__ bias){
    __shared__ __align__(16) uint32_t As[128*36];
    __shared__ __align__(16) uint32_t Bs[64*36];
    __shared__ float cw4[4][128];
    __shared__ int   ci4[4][128];
    int tile = blockIdx.x;
    int b  = tile / 288;
    int pp0 = (tile - b*288) * 128;
    int tid = threadIdx.x;
    int lane = tid & 31, warp = tid >> 5;
    int m0 = (warp & 3) * 32;
    int n0 = (warp >> 2) * 32;
    int g = lane >> 2, t = lane & 3;

    const uint32_t* xTb = g_xTh + (size_t)b*HW*32;

    float acc[2][4][4];
    #pragma unroll
    for (int mi=0;mi<2;mi++)
        #pragma unroll
        for (int ni=0;ni<4;ni++)
            #pragma unroll
            for (int j=0;j<4;j++) acc[mi][ni][j] = 0.f;

    for (int tap = 0; tap < 9; tap++){
        __syncthreads();       // As/Bs/cw4 free from previous tap
        if (tid < 128){
            int pix = tid;
            int pp = pp0 + pix;
            int gy = pp / Wn, gx = pp - (pp/Wn)*Wn;
            float dyv = g_om[((size_t)b*27 + 2*tap  )*HW + pp];
            float dxv = g_om[((size_t)b*27 + 2*tap+1)*HW + pp];
            float m   = g_om[((size_t)b*27 + 18+tap )*HW + pp];
            float py = (float)gy + (float)(tap/3 - 1) + dyv;
            float px = (float)gx + (float)(tap%3 - 1) + dxv;
            float fy = floorf(py), fx = floorf(px);
            int y0 = (int)fy, xq = (int)fx;
            float wy = py - fy, wx = px - fx;
            int y1 = y0+1, x1 = xq+1;
            int yc0 = min(max(y0,0),Hn-1), yc1 = min(max(y1,0),Hn-1);
            int xc0 = min(max(xq,0),Wn-1), xc1 = min(max(x1,0),Wn-1);
            float vy0 = (y0>=0 && y0<Hn)?1.f:0.f;
            float vy1 = (y1>=0 && y1<Hn)?1.f:0.f;
            float vx0 = (xq>=0 && xq<Wn)?1.f:0.f;
            float vx1 = (x1>=0 && x1<Wn)?1.f:0.f;
            cw4[0][pix] = (1.f-wy)*(1.f-wx)*vy0*vx0*m;  ci4[0][pix] = yc0*Wn+xc0;
            cw4[1][pix] = (1.f-wy)*wx     *vy0*vx1*m;   ci4[1][pix] = yc0*Wn+xc1;
            cw4[2][pix] = wy     *(1.f-wx)*vy1*vx0*m;   ci4[2][pix] = yc1*Wn+xc0;
            cw4[3][pix] = wy     *wx      *vy1*vx1*m;   ci4[3][pix] = yc1*Wn+xc1;
        }
        __syncthreads();
        // gather stage A: full 32 c2 per tap; 128 pix x 8 quads = 1024 tasks, uint4 loads
        #pragma unroll
        for (int it = 0; it < 4; it++){
            int id = tid + it*256;
            int q = id & 7, pix = id >> 3;
            float w0 = cw4[0][pix], w1 = cw4[1][pix], w2 = cw4[2][pix], w3 = cw4[3][pix];
            uint4 r0 = __ldg((const uint4*)(xTb + (size_t)ci4[0][pix]*32) + q);
            uint4 r1 = __ldg((const uint4*)(xTb + (size_t)ci4[1][pix]*32) + q);
            uint4 r2 = __ldg((const uint4*)(xTb + (size_t)ci4[2][pix]*32) + q);
            uint4 r3 = __ldg((const uint4*)(xTb + (size_t)ci4[3][pix]*32) + q);
            uint4 o;
            o.x = bil4(r0.x, r1.x, r2.x, r3.x, w0, w1, w2, w3);
            o.y = bil4(r0.y, r1.y, r2.y, r3.y, w0, w1, w2, w3);
            o.z = bil4(r0.z, r1.z, r2.z, r3.z, w0, w1, w2, w3);
            o.w = bil4(r0.w, r1.w, r2.w, r3.w, w0, w1, w2, w3);
            *(uint4*)&As[pix*36 + q*4] = o;
        }
        // stage B: 64 co x 8 quads = 512 tasks
        #pragma unroll
        for (int it = 0; it < 2; it++){
            int id = tid + it*256;
            int co = id >> 3, q = id & 7;
            *(uint4*)&Bs[co*36 + q*4] =
                __ldg((const uint4*)(g_wdcH + co*288 + tap*32) + q);
        }
        __syncthreads();
        #pragma unroll
        for (int kc = 0; kc < 4; kc++){
            uint32_t afr[2][4], bfr[4][2];
            #pragma unroll
            for (int mi=0;mi<2;mi++){
                int r = m0 + mi*16;
                afr[mi][0] = As[(r+g  )*36 + kc*8 + t];
                afr[mi][1] = As[(r+g+8)*36 + kc*8 + t];
                afr[mi][2] = As[(r+g  )*36 + kc*8 + t + 4];
                afr[mi][3] = As[(r+g+8)*36 + kc*8 + t + 4];
            }
            #pragma unroll
            for (int ni=0;ni<4;ni++){
                int cN = n0 + ni*8 + g;
                bfr[ni][0] = Bs[cN*36 + kc*8 + t];
                bfr[ni][1] = Bs[cN*36 + kc*8 + t + 4];
            }
            #pragma unroll
            for (int mi=0;mi<2;mi++)
                #pragma unroll
                for (int ni=0;ni<4;ni++)
                    mma_f16(acc[mi][ni], afr[mi], bfr[ni]);
        }
    }
    float* xdb = g_xd + (size_t)b*Cn*HW + pp0;
    #pragma unroll
    for (int mi=0;mi<2;mi++){
        int row = m0 + mi*16 + g;
        #pragma unroll
        for (int ni=0;ni<4;ni++){
            int col = n0 + ni*8 + 2*t;
            float b0 = __ldg(bias + col), b1 = __ldg(bias + col + 1);
            xdb[(size_t)col*HW     + row    ] = acc[mi][ni][0] + b0;
            xdb[(size_t)(col+1)*HW + row    ] = acc[mi][ni][1] + b1;
            xdb[(size_t)col*HW     + row + 8] = acc[mi][ni][2] + b0;
            xdb[(size_t)(col+1)*HW + row + 8] = acc[mi][ni][3] + b1;
        }
    }
}

// ---------------- channel mean ----------------
__global__ void __launch_bounds__(256) k_mean(){
    int bc = blockIdx.x;
    const float* p = g_xd + (size_t)bc*HW;
    float s = 0.f;
    for (int i=threadIdx.x; i<HW; i+=256) s += p[i];
    __shared__ float red[256];
    red[threadIdx.x] = s; __syncthreads();
    for (int o=128; o>0; o>>=1){
        if (threadIdx.x < o) red[threadIdx.x] += red[threadIdx.x+o];
        __syncthreads();
    }
    if (threadIdx.x==0) g_mean[bc] = red[0]*(1.f/HW);
}

// ---------------- channel attention MLP ----------------
__global__ void k_ca(const float* __restrict__ w1, const float* __restrict__ b1,
                     const float* __restrict__ w2, const float* __restrict__ b2){
    int b = blockIdx.x; int t = threadIdx.x;
    __shared__ float mn[64], h[8];
    mn[t] = g_mean[b*64+t];
    __syncthreads();
    if (t < 8){
        float s = __ldg(b1+t);
        for (int c=0;c<64;c++) s += __ldg(w1+t*64+c)*mn[c];
        h[t] = s > 0.f ? s : 0.f;
    }
    __syncthreads();
    float s = __ldg(b2+t);
    #pragma unroll
    for (int j=0;j<8;j++) s += __ldg(w2+t*8+j)*h[j];
    g_ca[b*64+t] = sigmoidf_(s);
}

// ---------------- spatial attention + xa (half2 out) ----------------
__global__ void __launch_bounds__(256) k_saxa(const float* __restrict__ wsa,
                                              const float* __restrict__ bsa){
    __shared__ float sh[64*102];
    __shared__ float part[8][32];
    __shared__ float sav[32];
    int x0 = blockIdx.x*32, y = blockIdx.y, b = blockIdx.z;
    int tid = threadIdx.x;
    const float* xb = g_xd + (size_t)b*Cn*HW;
    for (int e=tid; e<64*102; e+=256){
        int ci = e/102; int r = e%102; int dy = r/34; int xx = r%34;
        int gy = y+dy-1, gx = x0+xx-1;
        sh[e] = (gy>=0 && gy<Hn && gx>=0 && gx<Wn) ? xb[ci*HW + gy*Wn + gx] : 0.f;
    }
    __syncthreads();
    int pix = tid&31, g = tid>>5;
    float acc = 0.f;
    for (int ci=g*8; ci<g*8+8; ci++){
        const float* s = sh + ci*102 + pix;
        const float* wp = wsa + ci*9;
        acc += s[0]*__ldg(wp+0) + s[1]*__ldg(wp+1) + s[2]*__ldg(wp+2)
             + s[34]*__ldg(wp+3) + s[35]*__ldg(wp+4) + s[36]*__ldg(wp+5)
             + s[68]*__ldg(wp+6) + s[69]*__ldg(wp+7) + s[70]*__ldg(wp+8);
    }
    part[g][pix] = acc;
    __syncthreads();
    if (g == 0){
        float t = __ldg(bsa);
        #pragma unroll
        for (int j=0;j<8;j++) t += part[j][pix];
        sav[pix] = sigmoidf_(t);
    }
    __syncthreads();
    float sa = sav[pix];
    #pragma unroll
    for (int j=0;j<4;j++){
        int co2 = g + j*8;
        int co  = co2*2;
        float v0 = sh[co*102     + 34 + pix + 1];
        float v1 = sh[(co+1)*102 + 34 + pix + 1];
        float a0 = v0 * (g_ca[b*64+co]   + sa);
        float a1 = v1 * (g_ca[b*64+co+1] + sa);
        g_xah[((size_t)b*32+co2)*HW + y*Wn + x0 + pix] = packh2(a0, a1);
    }
}

// ---------------- r1 (fp16 mma): 1x1 64->256, leaky, half2 out ----------------
__global__ void __launch_bounds__(256) k_r1mma(const float* __restrict__ bias){
    __shared__ uint32_t Asu[128*36];
    __shared__ uint32_t Bsu[64*36];
    int tile = blockIdx.x;
    int b  = tile / 288;
    int pp0 = (tile - b*288) * 128;
    int tid = threadIdx.x;
    int lane = tid & 31, warp = tid >> 5;
    int m0 = (warp & 3) * 32;
    int n0 = (warp >> 2) * 32;
    int g = lane >> 2, t = lane & 3;

    const uint32_t* xab = g_xah + (size_t)b*32*HW;

    #pragma unroll
    for (int it = 0; it < 16; it++){
        int id = tid + it*256;
        int pix = id & 127, c2 = id >> 7;
        Asu[pix*36 + c2] = __ldg(xab + (size_t)c2*HW + pp0 + pix);
    }

    for (int cob = 0; cob < 4; cob++){
        float acc[2][4][4];
        #pragma unroll
        for (int mi=0;mi<2;mi++)
            #pragma unroll
            for (int ni=0;ni<4;ni++)
                #pragma unroll
                for (int j=0;j<4;j++) acc[mi][ni][j] = 0.f;
        __syncthreads();
        #pragma unroll
        for (int it = 0; it < 8; it++){
            int id = tid + it*256;
            int co = id >> 5, c2 = id & 31;
            Bsu[co*36 + c2] = g_wr1H[(size_t)(cob*64+co)*32 + c2];
        }
        __syncthreads();
        #pragma unroll
        for (int kc = 0; kc < 4; kc++){
            uint32_t afr[2][4], bfr[4][2];
            #pragma unroll
            for (int mi=0;mi<2;mi++){
                int r = m0 + mi*16;
                afr[mi][0] = Asu[(r+g  )*36 + kc*8 + t];
                afr[mi][1] = Asu[(r+g+8)*36 + kc*8 + t];
                afr[mi][2] = Asu[(r+g  )*36 + kc*8 + t + 4];
                afr[mi][3] = Asu[(r+g+8)*36 + kc*8 + t + 4];
            }
            #pragma unroll
            for (int ni=0;ni<4;ni++){
                int cN = n0 + ni*8 + g;
                bfr[ni][0] = Bsu[cN*36 + kc*8 + t];
                bfr[ni][1] = Bsu[cN*36 + kc*8 + t + 4];
            }
            #pragma unroll
            for (int mi=0;mi<2;mi++)
                #pragma unroll
                for (int ni=0;ni<4;ni++)
                    mma_f16(acc[mi][ni], afr[mi], bfr[ni]);
        }
        uint32_t* t1b = g_t1h + (size_t)b*128*HW + pp0;
        #pragma unroll
        for (int mi=0;mi<2;mi++){
            int row = m0 + mi*16 + g;
            #pragma unroll
            for (int ni=0;ni<4;ni++){
                int col = cob*64 + n0 + ni*8 + 2*t;
                int co2 = col >> 1;
                float b0 = __ldg(bias + col), b1 = __ldg(bias + col + 1);
                t1b[(size_t)co2*HW + row    ] = packh2(leakyf_(acc[mi][ni][0]+b0),
                                                       leakyf_(acc[mi][ni][1]+b1));
                t1b[(size_t)co2*HW + row + 8] = packh2(leakyf_(acc[mi][ni][2]+b0),
                                                       leakyf_(acc[mi][ni][3]+b1));
            }
        }
    }
}

// ---------------- r2 (fp16 halo mma): 3x3 256->64 ----------------
__global__ void __launch_bounds__(256) k_r2mma(const float* __restrict__ bias){
    __shared__ uint32_t Ahu[180*20];
    __shared__ __align__(16) uint32_t Bsu[2][64*20];
    int X0 = blockIdx.x*16, Y0 = blockIdx.y*8, b = blockIdx.z;
    int tid = threadIdx.x;
    int lane = tid & 31, warp = tid >> 5;
    int m0 = (warp & 3) * 32;
    int n0 = (warp >> 2) * 32;
    int g = lane >> 2, t = lane & 3;
    int hb0 = (m0 >> 4)*18 + g;

    const uint32_t* t1b = g_t1h + (size_t)b*128*HW;

    float acc[2][4][4];
    #pragma unroll
    for (int mi=0;mi<2;mi++)
        #pragma unroll
        for (int ni=0;ni<4;ni++)
            #pragma unroll
            for (int j=0;j<4;j++) acc[mi][ni][j] = 0.f;

    for (int cb = 0; cb < 8; cb++){
        __syncthreads();
        for (int id = tid; id < 2880; id += 256){
            int c2 = id / 180, pk = id - c2*180;
            int hy = pk/18, hx = pk - hy*18;
            int gy = Y0 + hy - 1, gx = X0 + hx - 1;
            uint32_t v = 0u;
            if ((unsigned)gy < (unsigned)Hn && (unsigned)gx < (unsigned)Wn)
                v = __ldg(t1b + (size_t)(cb*16 + c2)*HW + gy*Wn + gx);
            Ahu[pk*20 + c2] = v;
        }
        // stage B tap0 -> buf0 : 64 co x 4 quads = 256 tasks
        {
            int co = tid >> 2, q = tid & 3;
            *(uint4*)&Bsu[0][co*20 + q*4] =
                __ldg((const uint4*)(g_wr2H + (size_t)co*1152 + cb*16) + q);
        }
        for (int tap = 0; tap < 9; tap++){
            __syncthreads();
            if (tap < 8){
                int co = tid >> 2, q = tid & 3;
                *(uint4*)&Bsu[(tap+1)&1][co*20 + q*4] =
                    __ldg((const uint4*)(g_wr2H + (size_t)co*1152 + (tap+1)*128 + cb*16) + q);
            }
            const uint32_t* B = Bsu[tap&1];
            int toff = (tap/3)*18 + tap - (tap/3)*3;
            #pragma unroll
            for (int kc = 0; kc < 2; kc++){
                uint32_t afr[2][4], bfr[4][2];
                #pragma unroll
                for (int mi=0;mi<2;mi++){
                    int hh = hb0 + mi*18 + toff;
                    afr[mi][0] = Ahu[hh*20 + kc*8 + t];
                    afr[mi][1] = Ahu[(hh+8)*20 + kc*8 + t];
                    afr[mi][2] = Ahu[hh*20 + kc*8 + t + 4];
                    afr[mi][3] = Ahu[(hh+8)*20 + kc*8 + t + 4];
                }
                #pragma unroll
                for (int ni=0;ni<4;ni++){
                    int cN = n0 + ni*8 + g;
                    bfr[ni][0] = B[cN*20 + kc*8 + t];
                    bfr[ni][1] = B[cN*20 + kc*8 + t + 4];
                }
                #pragma unroll
                for (int mi=0;mi<2;mi++)
                    #pragma unroll
                    for (int ni=0;ni<4;ni++)
                        mma_f16(acc[mi][ni], afr[mi], bfr[ni]);
            }
        }
    }
    float* xrb = g_xr + (size_t)b*Cn*HW;
    int ybase = Y0 + (m0 >> 4);
    #pragma unroll
    for (int mi=0;mi<2;mi++){
        int q0 = (ybase + mi)*Wn + X0 + g;
        #pragma unroll
        for (int ni=0;ni<4;ni++){
            int col = n0 + ni*8 + 2*t;
            float b0 = __ldg(bias + col), b1 = __ldg(bias + col + 1);
            xrb[(size_t)col*HW     + q0    ] = acc[mi][ni][0] + b0;
            xrb[(size_t)(col+1)*HW + q0    ] = acc[mi][ni][1] + b1;
            xrb[(size_t)col*HW     + q0 + 8] = acc[mi][ni][2] + b0;
            xrb[(size_t)(col+1)*HW + q0 + 8] = acc[mi][ni][3] + b1;
        }
    }
}

// ---------------- n1: 1x1, 64 -> 32 (reads half2 xa) ----------------
__global__ void __launch_bounds__(256) k_n1(const float* __restrict__ bias){
    __shared__ uint32_t shu[32*32];
    int p0 = blockIdx.x*32; int b = p0/HW; int sp = p0%HW;
    int tid = threadIdx.x;
    for (int e=tid; e<1024; e+=256){
        int c2 = e>>5, pix = e&31;
        shu[e] = __ldg(g_xah + ((size_t)b*32+c2)*HW + sp + pix);
    }
    __syncthreads();
    int pix = tid&31, g = tid>>5;
    int co0 = g*4;
    float acc[4];
    #pragma unroll
    for (int j=0;j<4;j++) acc[j] = __ldg(bias+co0+j);
    #pragma unroll 8
    for (int c2=0; c2<32; c2++){
        float2 f = unpackh2(shu[c2*32+pix]);
        int ci = 2*c2;
        #pragma unroll
        for (int j=0;j<4;j++)
            acc[j] += f.x*__ldg(&g_wn1T[ci*32+co0+j]) + f.y*__ldg(&g_wn1T[(ci+1)*32+co0+j]);
    }
    #pragma unroll
    for (int j=0;j<4;j++)
        g_n1[((size_t)b*CH+co0+j)*HW + sp + pix] = acc[j];
}

// ---------------- n2: depthwise 3x3 ----------------
__global__ void __launch_bounds__(256) k_n2(const float* __restrict__ w,
                                            const float* __restrict__ bias){
    int idx = blockIdx.x*256 + threadIdx.x;
    if (idx >= Bn*CH*HW) return;
    int pp = idx % HW; int bc = idx / HW; int c = bc % CH;
    int gy = pp/Wn, gx = pp%Wn;
    const float* in = g_n1 + (size_t)bc*HW;
    float acc = __ldg(bias+c);
    #pragma unroll
    for (int ky=0;ky<3;ky++){
        int yy = gy+ky-1;
        if (yy<0 || yy>=Hn) continue;
        #pragma unroll
        for (int kx=0;kx<3;kx++){
            int xx = gx+kx-1;
            if (xx<0 || xx>=Wn) continue;
            acc += in[yy*Wn+xx]*__ldg(w + c*9 + ky*3 + kx);
        }
    }
    g_n2[idx] = acc;
}

// ---------------- final: out = x + xr + (1x1 32->64)(n2) ----------------
__global__ void __launch_bounds__(256) k_final(const float* __restrict__ x,
                                               const float* __restrict__ bias,
                                               float* __restrict__ out){
    __shared__ float sh[32*32];
    int p0 = blockIdx.x*32; int b = p0/HW; int sp = p0%HW;
    int tid = threadIdx.x;
    for (int e=tid; e<32*32; e+=256){
        int ci=e>>5, pix=e&31;
        sh[e] = g_n2[((size_t)b*CH+ci)*HW + sp + pix];
    }
    __syncthreads();
    int pix = tid&31, g = tid>>5;
    int co0 = g*8;
    float acc[8];
    #pragma unroll
    for (int j=0;j<8;j++) acc[j] = __ldg(bias+co0+j);
    #pragma unroll 4
    for (int ci=0; ci<32; ci++){
        float v = sh[ci*32+pix];
        float4 wa = *(const float4*)&g_wn3T[ci*64+co0];
        float4 wb = *(const float4*)&g_wn3T[ci*64+co0+4];
        acc[0]+=v*wa.x; acc[1]+=v*wa.y; acc[2]+=v*wa.z; acc[3]+=v*wa.w;
        acc[4]+=v*wb.x; acc[5]+=v*wb.y; acc[6]+=v*wb.z; acc[7]+=v*wb.w;
    }
    #pragma unroll
    for (int j=0;j<8;j++){
        size_t o = ((size_t)b*64+co0+j)*HW + sp + pix;
        out[o] = x[o] + g_xr[o] + acc[j];
    }
}

// ---------------- launch ----------------
extern "C" void kernel_launch(void* const* d_in, const int* in_sizes, int n_in,
                              void* d_out, int out_size){
    const float* x     = (const float*)d_in[0];
    const float* w_off = (const float*)d_in[1];
    const float* b_off = (const float*)d_in[2];
    const float* w_dc  = (const float*)d_in[3];
    const float* b_dc  = (const float*)d_in[4];
    const float* w_ca1 = (const float*)d_in[5];
    const float* b_ca1 = (const float*)d_in[6];
    const float* w_ca2 = (const float*)d_in[7];
    const float* b_ca2 = (const float*)d_in[8];
    const float* w_sa  = (const float*)d_in[9];
    const float* b_sa  = (const float*)d_in[10];
    const float* w_r1  = (const float*)d_in[11];
    const float* b_r1  = (const float*)d_in[12];
    const float* w_r2  = (const float*)d_in[13];
    const float* b_r2  = (const float*)d_in[14];
    const float* w_n1  = (const float*)d_in[15];
    const float* b_n1  = (const float*)d_in[16];
    const float* w_n2  = (const float*)d_in[17];
    const float* b_n2  = (const float*)d_in[18];
    const float* w_n3  = (const float*)d_in[19];
    const float* b_n3  = (const float*)d_in[20];
    float* out = (float*)d_out;

    k_prep<<<256, 256>>>(w_off, w_dc, w_r2, w_r1, w_n1, w_n3);
    k_tr<<<(Bn*HW)/128, 256>>>(x);
    k_offmma<<<dim3(12, 24, Bn), 256>>>(b_off);
    k_deform_mma<<<1152, 256>>>(b_dc);
    k_mean<<<Bn*Cn, 256>>>();
    k_ca<<<Bn, 64>>>(w_ca1, b_ca1, w_ca2, b_ca2);
    k_saxa<<<dim3(Wn/32, Hn, Bn), 256>>>(w_sa, b_sa);
    k_r1mma<<<1152, 256>>>(b_r1);
    k_r2mma<<<dim3(12, 24, Bn), 256>>>(b_r2);
    k_n1<<<(Bn*HW)/32, 256>>>(b_n1);
    k_n2<<<(Bn*CH*HW + 255)/256, 256>>>(w_n2, b_n2);
    k_final<<<(Bn*HW)/32, 256>>>(x, b_n3, out);
}